// round 1
// baseline (speedup 1.0000x reference)
#include <cuda_runtime.h>
#include <math.h>

#define BATCH 16384
#define TT 7
#define DD 1024
#define HH 512
#define EE 64
#define NF 4
#define G4H 2048              // 4*H
#define KCOMB 1540            // D + H + 4

// Output offsets (float32 concat in reference return order)
#define OFF_TOPP  ((size_t)0)
#define OFF_TOPI  ((size_t)131072)
#define OFF_LOSS  ((size_t)262144)
#define OFF_FLOW  ((size_t)262145)
#define OFF_USAGE ((size_t)327681)
#define OFF_ADJ   ((size_t)327745)

// ------------------------- scratch (static, no allocs) -------------------------
__device__ float d_XS[(size_t)BATCH * TT * G4H];   // input projections, all timesteps
__device__ float d_GATES[(size_t)BATCH * G4H];     // per-step gates
__device__ float d_Hst[(size_t)BATCH * HH];
__device__ float d_Cst[(size_t)BATCH * HH];
__device__ float d_FH[(size_t)BATCH * HH];         // flow hidden (post relu)
__device__ float d_FLOW[(size_t)BATCH * NF];       // flow_state
__device__ float d_COMB[(size_t)BATCH * KCOMB];    // concat [x | h | flow]
__device__ float d_G1[(size_t)BATCH * DD];         // gate hidden
__device__ float d_ADJ[(size_t)BATCH * EE];        // gate_logits (incl. gb2)
__device__ float d_BSUM[G4H];                      // b_ih + b_hh

// ------------------------- generic fp32 NT GEMM -------------------------
// C[m,n] = sum_k A[m,k]*W[n,k] (+bias[n]) (+addend[m,n]) (relu)
template<int BM, int BN, int BK, int TM, int TN>
__global__ void __launch_bounds__((BM/TM)*(BN/TN))
gemm_nt(const float* __restrict__ A, int lda,
        const float* __restrict__ W, int ldw,
        float* __restrict__ C, int ldc, int K,
        const float* __restrict__ bias,
        const float* __restrict__ addend, int add_ld,
        int relu)
{
    constexpr int NTH = (BM/TM)*(BN/TN);
    __shared__ float As[BK][BM];
    __shared__ float Ws[BK][BN];

    const int tid = threadIdx.x;
    const int m0 = blockIdx.y * BM;
    const int n0 = blockIdx.x * BN;

    float acc[TM][TN];
#pragma unroll
    for (int i = 0; i < TM; i++)
#pragma unroll
        for (int j = 0; j < TN; j++) acc[i][j] = 0.f;

    const int ty = tid / (BN/TN);
    const int tx = tid % (BN/TN);

    for (int k0 = 0; k0 < K; k0 += BK) {
        // load A tile (coalesced float4 along K)
#pragma unroll
        for (int q = tid; q < BM*BK/4; q += NTH) {
            int row = q / (BK/4);
            int kq  = (q % (BK/4)) * 4;
            float4 v = make_float4(0.f, 0.f, 0.f, 0.f);
            if (k0 + kq < K)
                v = *reinterpret_cast<const float4*>(A + (size_t)(m0+row)*lda + k0 + kq);
            As[kq+0][row] = v.x; As[kq+1][row] = v.y;
            As[kq+2][row] = v.z; As[kq+3][row] = v.w;
        }
        // load W tile
#pragma unroll
        for (int q = tid; q < BN*BK/4; q += NTH) {
            int row = q / (BK/4);
            int kq  = (q % (BK/4)) * 4;
            float4 v = make_float4(0.f, 0.f, 0.f, 0.f);
            if (k0 + kq < K)
                v = *reinterpret_cast<const float4*>(W + (size_t)(n0+row)*ldw + k0 + kq);
            Ws[kq+0][row] = v.x; Ws[kq+1][row] = v.y;
            Ws[kq+2][row] = v.z; Ws[kq+3][row] = v.w;
        }
        __syncthreads();

#pragma unroll
        for (int k = 0; k < BK; k++) {
            float a[TM], w[TN];
#pragma unroll
            for (int i = 0; i < TM; i++) a[i] = As[k][ty*TM + i];
#pragma unroll
            for (int j = 0; j < TN; j++) w[j] = Ws[k][tx*TN + j];
#pragma unroll
            for (int i = 0; i < TM; i++)
#pragma unroll
                for (int j = 0; j < TN; j++)
                    acc[i][j] = fmaf(a[i], w[j], acc[i][j]);
        }
        __syncthreads();
    }

#pragma unroll
    for (int i = 0; i < TM; i++) {
        int m = m0 + ty*TM + i;
#pragma unroll
        for (int j = 0; j < TN; j++) {
            int n = n0 + tx*TN + j;
            float v = acc[i][j];
            if (bias)   v += bias[n];
            if (addend) v += addend[(size_t)m*add_ld + n];
            if (relu)   v = fmaxf(v, 0.f);
            C[(size_t)m*ldc + n] = v;
        }
    }
}

// ------------------------- small kernels -------------------------
__global__ void bias_sum_kernel(const float* __restrict__ b_ih,
                                const float* __restrict__ b_hh,
                                float* __restrict__ bsum) {
    int i = blockIdx.x * blockDim.x + threadIdx.x;
    if (i < G4H) bsum[i] = b_ih[i] + b_hh[i];
}

__global__ void zero_kernel(float* __restrict__ p, size_t n) {
    size_t i = (size_t)blockIdx.x * blockDim.x + threadIdx.x;
    if (i < n) p[i] = 0.f;
}

__device__ __forceinline__ float sigmoidf(float x) { return 1.f / (1.f + expf(-x)); }

__global__ void lstm_pw(const float* __restrict__ gates, int rstride,
                        float* __restrict__ Hs, float* __restrict__ Cs) {
    int idx = blockIdx.x * blockDim.x + threadIdx.x;
    if (idx >= BATCH * HH) return;
    int b = idx / HH, j = idx % HH;
    const float* g = gates + (size_t)b * rstride;
    float gi = g[j], gf = g[HH + j], gg = g[2*HH + j], go = g[3*HH + j];
    float c = sigmoidf(gf) * Cs[idx] + sigmoidf(gi) * tanhf(gg);
    Cs[idx] = c;
    Hs[idx] = sigmoidf(go) * tanhf(c);
}

// flow head: y = FH @ fw2^T + fb2, softmax over 4. One warp per row.
__global__ void flow2_kernel(const float* __restrict__ FHp,
                             const float* __restrict__ fw2,
                             const float* __restrict__ fb2,
                             float* __restrict__ FLOWp,
                             float* __restrict__ out) {
    __shared__ float w[NF * HH];
    int tid = threadIdx.x;
    for (int q = tid; q < NF*HH; q += blockDim.x) w[q] = fw2[q];
    __syncthreads();
    int warp = tid >> 5, lane = tid & 31;
    int b = blockIdx.x * 8 + warp;
    const float* r = FHp + (size_t)b * HH;
    float a0 = 0.f, a1 = 0.f, a2 = 0.f, a3 = 0.f;
    for (int k = lane; k < HH; k += 32) {
        float v = r[k];
        a0 += v * w[k];
        a1 += v * w[HH + k];
        a2 += v * w[2*HH + k];
        a3 += v * w[3*HH + k];
    }
#pragma unroll
    for (int off = 16; off; off >>= 1) {
        a0 += __shfl_xor_sync(0xffffffffu, a0, off);
        a1 += __shfl_xor_sync(0xffffffffu, a1, off);
        a2 += __shfl_xor_sync(0xffffffffu, a2, off);
        a3 += __shfl_xor_sync(0xffffffffu, a3, off);
    }
    if (lane == 0) {
        a0 += fb2[0]; a1 += fb2[1]; a2 += fb2[2]; a3 += fb2[3];
        float m = fmaxf(fmaxf(a0, a1), fmaxf(a2, a3));
        float e0 = expf(a0 - m), e1 = expf(a1 - m), e2 = expf(a2 - m), e3 = expf(a3 - m);
        float inv = 1.f / (e0 + e1 + e2 + e3);
        float p0 = e0*inv, p1 = e1*inv, p2 = e2*inv, p3 = e3*inv;
        FLOWp[b*4+0] = p0; FLOWp[b*4+1] = p1; FLOWp[b*4+2] = p2; FLOWp[b*4+3] = p3;
        out[OFF_FLOW + b*4 + 0] = p0; out[OFF_FLOW + b*4 + 1] = p1;
        out[OFF_FLOW + b*4 + 2] = p2; out[OFF_FLOW + b*4 + 3] = p3;
    }
}

__global__ void build_comb(const float* __restrict__ x,
                           const float* __restrict__ Hs,
                           const float* __restrict__ FLOWp,
                           float* __restrict__ comb) {
    size_t idx = (size_t)blockIdx.x * blockDim.x + threadIdx.x;
    if (idx >= (size_t)BATCH * KCOMB) return;
    int b = (int)(idx / KCOMB), c = (int)(idx % KCOMB);
    float v;
    if (c < DD)            v = x[(size_t)b*DD + c];
    else if (c < DD + HH)  v = Hs[(size_t)b*HH + (c - DD)];
    else                   v = FLOWp[b*4 + (c - DD - HH)];
    comb[idx] = v;
}

// Final gating: adjusted logits, softmax(64), usage accumulation, top-8.
// One warp per row, 8 rows per block.
__global__ void final_gate_kernel(const float* __restrict__ adjraw,
                                  const float* __restrict__ flow,
                                  const float* __restrict__ spec,
                                  float* __restrict__ out) {
    __shared__ float s_spec[EE * NF];
    __shared__ float s_usage[EE];
    int tid = threadIdx.x;
    if (tid < EE*NF) s_spec[tid] = spec[tid];
    if (tid < EE)    s_usage[tid] = 0.f;
    __syncthreads();

    int warp = tid >> 5, lane = tid & 31;
    int b = blockIdx.x * 8 + warp;

    float f0 = flow[b*4+0], f1 = flow[b*4+1], f2 = flow[b*4+2], f3 = flow[b*4+3];
    int e0 = lane, e1 = lane + 32;
    float sp0 = 0.1f * (f0*s_spec[e0*4+0] + f1*s_spec[e0*4+1] + f2*s_spec[e0*4+2] + f3*s_spec[e0*4+3]);
    float sp1 = 0.1f * (f0*s_spec[e1*4+0] + f1*s_spec[e1*4+1] + f2*s_spec[e1*4+2] + f3*s_spec[e1*4+3]);
    float l0 = adjraw[(size_t)b*EE + e0] + sp0;
    float l1 = adjraw[(size_t)b*EE + e1] + sp1;
    out[OFF_ADJ + (size_t)b*EE + e0] = l0;
    out[OFF_ADJ + (size_t)b*EE + e1] = l1;

    float m = fmaxf(l0, l1);
#pragma unroll
    for (int off = 16; off; off >>= 1) m = fmaxf(m, __shfl_xor_sync(0xffffffffu, m, off));
    float x0 = expf(l0 - m), x1 = expf(l1 - m);
    float s = x0 + x1;
#pragma unroll
    for (int off = 16; off; off >>= 1) s += __shfl_xor_sync(0xffffffffu, s, off);
    float inv_s = 1.f / s;
    float p0 = x0 * inv_s, p1 = x1 * inv_s;

    atomicAdd(&s_usage[e0], p0);
    atomicAdd(&s_usage[e1], p1);

    // top-8 by repeated warp argmax (ties -> lower index, matches lax.top_k)
    float tp[8]; int ti[8];
    float v0 = p0, v1 = p1;
#pragma unroll
    for (int it = 0; it < 8; it++) {
        float v; int bi;
        if (v1 > v0) { v = v1; bi = e1; } else { v = v0; bi = e0; }
#pragma unroll
        for (int off = 16; off; off >>= 1) {
            float ov = __shfl_xor_sync(0xffffffffu, v, off);
            int   oi = __shfl_xor_sync(0xffffffffu, bi, off);
            if (ov > v || (ov == v && oi < bi)) { v = ov; bi = oi; }
        }
        tp[it] = v; ti[it] = bi;
        if (bi == e0) v0 = -1.f;
        if (bi == e1) v1 = -1.f;
    }
    float ssum = 0.f;
#pragma unroll
    for (int it = 0; it < 8; it++) ssum += tp[it];
    float invn = 1.f / (ssum + 1e-8f);
    if (lane < 8) {
        out[OFF_TOPP + (size_t)b*8 + lane] = tp[lane] * invn;
        out[OFF_TOPI + (size_t)b*8 + lane] = (float)ti[lane];
    }
    __syncthreads();
    if (tid < EE) atomicAdd(&out[OFF_USAGE + tid], s_usage[tid]);
}

__global__ void loss_kernel(float* __restrict__ out) {
    __shared__ float red[EE];
    int t = threadIdx.x;  // 64 threads
    float u = out[OFF_USAGE + t] / (float)BATCH;
    out[OFF_USAGE + t] = u;
    // (1/64)*(log(1/64) - log(u)) = -(1/64)*log1p(64u - 1)  (cancellation-safe)
    red[t] = -(1.0f / 64.f) * log1pf(64.f * u - 1.f);
    __syncthreads();
    for (int s = 32; s; s >>= 1) {
        if (t < s) red[t] += red[t + s];
        __syncthreads();
    }
    if (t == 0) out[OFF_LOSS] = red[0] / 64.f;
}

// ------------------------- launch -------------------------
extern "C" void kernel_launch(void* const* d_in, const int* in_sizes, int n_in,
                              void* d_out, int out_size) {
    const float* x        = (const float*)d_in[0];
    const float* context  = (const float*)d_in[1];
    const float* W_ih     = (const float*)d_in[2];
    const float* W_hh     = (const float*)d_in[3];
    const float* b_ih     = (const float*)d_in[4];
    const float* b_hh     = (const float*)d_in[5];
    const float* fw1      = (const float*)d_in[6];
    const float* fb1      = (const float*)d_in[7];
    const float* fw2      = (const float*)d_in[8];
    const float* fb2      = (const float*)d_in[9];
    const float* gw1      = (const float*)d_in[10];
    const float* gb1      = (const float*)d_in[11];
    const float* gw2      = (const float*)d_in[12];
    const float* gb2      = (const float*)d_in[13];
    const float* espec    = (const float*)d_in[14];
    float* out = (float*)d_out;

    float *XS, *GATES, *Hs, *Cs, *FH, *FLOW, *COMB, *G1, *ADJ, *BSUM;
    cudaGetSymbolAddress((void**)&XS,    d_XS);
    cudaGetSymbolAddress((void**)&GATES, d_GATES);
    cudaGetSymbolAddress((void**)&Hs,    d_Hst);
    cudaGetSymbolAddress((void**)&Cs,    d_Cst);
    cudaGetSymbolAddress((void**)&FH,    d_FH);
    cudaGetSymbolAddress((void**)&FLOW,  d_FLOW);
    cudaGetSymbolAddress((void**)&COMB,  d_COMB);
    cudaGetSymbolAddress((void**)&G1,    d_G1);
    cudaGetSymbolAddress((void**)&ADJ,   d_ADJ);
    cudaGetSymbolAddress((void**)&BSUM,  d_BSUM);

    // bias sum + zero c state
    bias_sum_kernel<<<(G4H + 255)/256, 256>>>(b_ih, b_hh, BSUM);
    zero_kernel<<<((size_t)BATCH*HH + 255)/256, 256>>>(Cs, (size_t)BATCH*HH);

    // XS = context @ W_ih^T + (b_ih + b_hh), rows are (b*T + t)
    gemm_nt<128,128,16,8,8><<<dim3(G4H/128, (BATCH*TT)/128), 256>>>(
        context, DD, W_ih, DD, XS, G4H, DD, BSUM, nullptr, 0, 0);

    // t = 0: gates come straight from XS (h0 = 0)
    lstm_pw<<<(BATCH*HH + 255)/256, 256>>>(XS + 0, TT*G4H, Hs, Cs);

    for (int t = 1; t < TT; t++) {
        // GATES = Hs @ W_hh^T + XS[:, t, :]
        gemm_nt<128,128,16,8,8><<<dim3(G4H/128, BATCH/128), 256>>>(
            Hs, HH, W_hh, HH, GATES, G4H, HH, nullptr, XS + (size_t)t*G4H, TT*G4H, 0);
        lstm_pw<<<(BATCH*HH + 255)/256, 256>>>(GATES, G4H, Hs, Cs);
    }

    // flow hidden: relu(x @ fw1^T + fb1)
    gemm_nt<128,128,16,8,8><<<dim3(HH/128, BATCH/128), 256>>>(
        x, DD, fw1, DD, FH, HH, DD, fb1, nullptr, 0, 1);

    // flow_state softmax head
    flow2_kernel<<<BATCH/8, 256>>>(FH, fw2, fb2, FLOW, out);

    // combined = [x | h | flow]
    build_comb<<<(unsigned)(((size_t)BATCH*KCOMB + 255)/256), 256>>>(x, Hs, FLOW, COMB);

    // gate hidden: relu(combined @ gw1^T + gb1)  (K = 1540, ragged tile handled)
    gemm_nt<128,128,16,8,8><<<dim3(DD/128, BATCH/128), 256>>>(
        COMB, KCOMB, gw1, KCOMB, G1, DD, KCOMB, gb1, nullptr, 0, 1);

    // gate logits: G1 @ gw2^T + gb2
    gemm_nt<128,64,16,8,4><<<dim3(EE/64, BATCH/128), 256>>>(
        G1, DD, gw2, DD, ADJ, EE, DD, gb2, nullptr, 0, 0);

    // zero usage accumulator region of output, then finalize
    zero_kernel<<<1, 64>>>(out + OFF_USAGE, EE);
    final_gate_kernel<<<BATCH/8, 256>>>(ADJ, FLOW, espec, out);
    loss_kernel<<<1, 64>>>(out);
}

// round 6
// speedup vs baseline: 1.1509x; 1.1509x over previous
#include <cuda_runtime.h>
#include <cstdint>
#include <math.h>

#define BATCH 16384
#define TT 7
#define DD 1024
#define HH 512
#define EE 64
#define NF 4
#define G4H 2048              // 4*H
#define KCOMB 1540            // D + H + 4

// Output offsets (float32 concat in reference return order)
#define OFF_TOPP  ((size_t)0)
#define OFF_TOPI  ((size_t)131072)
#define OFF_LOSS  ((size_t)262144)
#define OFF_FLOW  ((size_t)262145)
#define OFF_USAGE ((size_t)327681)
#define OFF_ADJ   ((size_t)327745)

// ------------------------- scratch (static, no allocs) -------------------------
__device__ float d_XS[(size_t)BATCH * TT * G4H];
__device__ float d_GATES[(size_t)BATCH * G4H];
__device__ float d_Hst[(size_t)BATCH * HH];
__device__ float d_Cst[(size_t)BATCH * HH];
__device__ float d_FH[(size_t)BATCH * HH];
__device__ float d_FLOW[(size_t)BATCH * NF];
__device__ float d_COMB[(size_t)BATCH * KCOMB];
__device__ float d_G1[(size_t)BATCH * DD];
__device__ float d_ADJ[(size_t)BATCH * EE];
__device__ float d_BSUM[G4H];

// ------------------------- helpers -------------------------
__device__ __forceinline__ uint32_t smem_u32(const void* p) {
    uint32_t a;
    asm("{ .reg .u64 t; cvta.to.shared.u64 t, %1; cvt.u32.u64 %0, t; }" : "=r"(a) : "l"(p));
    return a;
}
__device__ __forceinline__ void ldsm_x4(uint32_t* r, uint32_t addr) {
    asm volatile("ldmatrix.sync.aligned.m8n8.x4.shared.b16 {%0,%1,%2,%3}, [%4];"
        : "=r"(r[0]), "=r"(r[1]), "=r"(r[2]), "=r"(r[3]) : "r"(addr));
}
// tf32 mma: A 4 regs (m16k8), B 2 regs (k8n8), C 4 f32
__device__ __forceinline__ void mma1688(float* c, const uint32_t* a,
                                        uint32_t b0, uint32_t b1) {
    asm volatile(
        "mma.sync.aligned.m16n8k8.row.col.f32.tf32.tf32.f32 "
        "{%0,%1,%2,%3}, {%4,%5,%6,%7}, {%8,%9}, {%0,%1,%2,%3};"
        : "+f"(c[0]), "+f"(c[1]), "+f"(c[2]), "+f"(c[3])
        : "r"(a[0]), "r"(a[1]), "r"(a[2]), "r"(a[3]), "r"(b0), "r"(b1));
}
__device__ __forceinline__ float tf32_rnd(float v) {
    float r; asm("cvt.rna.tf32.f32 %0, %1;" : "=f"(r) : "f"(v)); return r;
}
// split fp32 -> tf32 hi + tf32 lo (no scaling; tf32 has full fp32 exponent range)
__device__ __forceinline__ void tsplit(float v, float& h, float& l) {
    h = tf32_rnd(v);
    l = tf32_rnd(v - h);
}

// ------------------------- mma.sync 4xTF32 GEMM -------------------------
// C[m,n] = sum_k A[m,k]*W[n,k] (+bias[n]) (+addend[m,n]) (relu)
// BM=128, BK=32 fp32-k per chunk; BN in {128, 64}. Warp tile 32x32.
template<int BN>
__global__ void __launch_bounds__(128 * (BN / 32), 1)
gemm_mma(const float* __restrict__ A, int lda,
         const float* __restrict__ W, int ldw,
         float* __restrict__ C, int ldc, int K,
         const float* __restrict__ bias,
         const float* __restrict__ addend, int add_ld,
         int relu)
{
    constexpr int BM = 128, BK = 32;
    constexpr int NW = 4 * (BN / 32);
    constexpr int T = 32 * NW;
    constexpr int PITCHB = 144;             // 32 floats + 4 pad floats (bytes)
    constexpr int A_HALF = BM * PITCHB;     // one A sub-tile (hi or lo)
    constexpr int B_HALF = BN * PITCHB;
    constexpr int STAGE = 2 * A_HALF + 2 * B_HALF;
    constexpr int AV = BM * BK / 4 / T;     // float4 loads/thread for A
    constexpr int BV = BN * BK / 4 / T;

    extern __shared__ char smem[];
    const uint32_t dsm = smem_u32(smem);

    const int tid = threadIdx.x;
    const int lane = tid & 31;
    const int wid = tid >> 5;
    const int wm = (wid & 3) * 32;
    const int wn = (wid >> 2) * 32;
    const long m0 = (long)blockIdx.y * BM;
    const int  n0 = blockIdx.x * BN;

    float Cacc[2][4][4];
#pragma unroll
    for (int i = 0; i < 2; i++)
#pragma unroll
        for (int j = 0; j < 4; j++)
#pragma unroll
            for (int q = 0; q < 4; q++) Cacc[i][j][q] = 0.f;

    float4 ra[AV], rb[BV];

    auto load_chunk = [&](int ch) {
        const int k0 = ch * BK;
#pragma unroll
        for (int q = 0; q < AV; q++) {
            int idx = tid + q * T;
            int row = idx >> 3, c4 = (idx & 7) * 4;
            ra[q] = (k0 + c4 < K)
                ? *reinterpret_cast<const float4*>(A + (m0 + row) * (long)lda + k0 + c4)
                : make_float4(0.f, 0.f, 0.f, 0.f);
        }
#pragma unroll
        for (int q = 0; q < BV; q++) {
            int idx = tid + q * T;
            int row = idx >> 3, c4 = (idx & 7) * 4;
            rb[q] = (k0 + c4 < K)
                ? *reinterpret_cast<const float4*>(W + (long)(n0 + row) * ldw + k0 + c4)
                : make_float4(0.f, 0.f, 0.f, 0.f);
        }
    };

    auto store_chunk = [&](int s) {
        char* aHi = smem + s * STAGE;
        char* aLo = aHi + A_HALF;
        char* bHi = aHi + 2 * A_HALF;
        char* bLo = bHi + B_HALF;
#pragma unroll
        for (int q = 0; q < AV; q++) {
            int idx = tid + q * T;
            int row = idx >> 3, c4 = (idx & 7) * 4;
            int off = row * PITCHB + c4 * 4;
            float4 h, l;
            tsplit(ra[q].x, h.x, l.x); tsplit(ra[q].y, h.y, l.y);
            tsplit(ra[q].z, h.z, l.z); tsplit(ra[q].w, h.w, l.w);
            *reinterpret_cast<float4*>(aHi + off) = h;
            *reinterpret_cast<float4*>(aLo + off) = l;
        }
#pragma unroll
        for (int q = 0; q < BV; q++) {
            int idx = tid + q * T;
            int row = idx >> 3, c4 = (idx & 7) * 4;
            int off = row * PITCHB + c4 * 4;
            float4 h, l;
            tsplit(rb[q].x, h.x, l.x); tsplit(rb[q].y, h.y, l.y);
            tsplit(rb[q].z, h.z, l.z); tsplit(rb[q].w, h.w, l.w);
            *reinterpret_cast<float4*>(bHi + off) = h;
            *reinterpret_cast<float4*>(bLo + off) = l;
        }
    };

    // ldmatrix per-lane offsets (byte gathers over fp32 tiles)
    // A x4: mats = {rows 0-7 k0-3 | rows 8-15 k0-3 | rows 0-7 k4-7 | rows 8-15 k4-7}
    const uint32_t a_l_off = (uint32_t)((lane & 15) * PITCHB + (lane >> 4) * 16);
    // B x4 over an n-frag pair: {frag p rows, frag p+1 rows} x {k0-3, k4-7}
    const uint32_t b_l_off = (uint32_t)((((lane >> 3) & 1) * 8 + (lane & 7)) * PITCHB
                                        + (lane >> 4) * 16);

    auto compute = [&](int s) {
        const uint32_t base = dsm + s * STAGE;
        const uint32_t aH = base + (uint32_t)(wm * PITCHB) + a_l_off;
        const uint32_t bH = base + 2 * A_HALF + (uint32_t)(wn * PITCHB) + b_l_off;
#pragma unroll
        for (int ks = 0; ks < 4; ks++) {
            uint32_t ah[2][4], al[2][4];
            uint32_t bh[4][2], bl[4][2];
#pragma unroll
            for (int mi = 0; mi < 2; mi++) {
                uint32_t ad = aH + mi * 16 * PITCHB + ks * 32;
                ldsm_x4(ah[mi], ad);
                ldsm_x4(al[mi], ad + A_HALF);
            }
#pragma unroll
            for (int p = 0; p < 2; p++) {
                uint32_t bd = bH + p * 16 * PITCHB + ks * 32;
                uint32_t t[4];
                ldsm_x4(t, bd);
                bh[2*p][0] = t[0]; bh[2*p][1] = t[2];
                bh[2*p+1][0] = t[1]; bh[2*p+1][1] = t[3];
                ldsm_x4(t, bd + B_HALF);
                bl[2*p][0] = t[0]; bl[2*p][1] = t[2];
                bl[2*p+1][0] = t[1]; bl[2*p+1][1] = t[3];
            }
#pragma unroll
            for (int mi = 0; mi < 2; mi++)
#pragma unroll
                for (int ni = 0; ni < 4; ni++) {
                    mma1688(Cacc[mi][ni], ah[mi], bh[ni][0], bh[ni][1]);
                    mma1688(Cacc[mi][ni], ah[mi], bl[ni][0], bl[ni][1]);
                    mma1688(Cacc[mi][ni], al[mi], bh[ni][0], bh[ni][1]);
                    mma1688(Cacc[mi][ni], al[mi], bl[ni][0], bl[ni][1]);
                }
        }
    };

    const int nch = (K + BK - 1) / BK;

    load_chunk(0);
    store_chunk(0);
    __syncthreads();

    for (int i = 0; i < nch; i++) {
        const int s = i & 1;
        if (i + 1 < nch) load_chunk(i + 1);
        compute(s);
        if (i + 1 < nch) {
            store_chunk(s ^ 1);
            __syncthreads();
        }
    }

    // epilogue (+bias)(+addend)(relu)
#pragma unroll
    for (int mi = 0; mi < 2; mi++)
#pragma unroll
        for (int ni = 0; ni < 4; ni++)
#pragma unroll
            for (int h = 0; h < 2; h++) {
                long row = m0 + wm + mi * 16 + (lane >> 2) + h * 8;
                int  col = n0 + wn + ni * 8 + (lane & 3) * 2;
                float v0 = Cacc[mi][ni][2 * h + 0];
                float v1 = Cacc[mi][ni][2 * h + 1];
                if (bias) { v0 += bias[col]; v1 += bias[col + 1]; }
                if (addend) {
                    float2 ad = *reinterpret_cast<const float2*>(addend + row * (long)add_ld + col);
                    v0 += ad.x; v1 += ad.y;
                }
                if (relu) { v0 = fmaxf(v0, 0.f); v1 = fmaxf(v1, 0.f); }
                *reinterpret_cast<float2*>(C + row * (long)ldc + col) = make_float2(v0, v1);
            }
}

// ------------------------- small kernels -------------------------
__global__ void bias_sum_kernel(const float* __restrict__ b_ih,
                                const float* __restrict__ b_hh,
                                float* __restrict__ bsum) {
    int i = blockIdx.x * blockDim.x + threadIdx.x;
    if (i < G4H) bsum[i] = b_ih[i] + b_hh[i];
}

__global__ void zero_kernel(float* __restrict__ p, size_t n) {
    size_t i = (size_t)blockIdx.x * blockDim.x + threadIdx.x;
    if (i < n) p[i] = 0.f;
}

__device__ __forceinline__ float sigmoidf(float x) { return 1.f / (1.f + expf(-x)); }

__global__ void lstm_pw(const float* __restrict__ gates, int rstride,
                        float* __restrict__ Hs, float* __restrict__ Cs) {
    int idx = blockIdx.x * blockDim.x + threadIdx.x;
    if (idx >= BATCH * HH) return;
    int b = idx / HH, j = idx % HH;
    const float* g = gates + (size_t)b * rstride;
    float gi = g[j], gf = g[HH + j], gg = g[2 * HH + j], go = g[3 * HH + j];
    float c = sigmoidf(gf) * Cs[idx] + sigmoidf(gi) * tanhf(gg);
    Cs[idx] = c;
    Hs[idx] = sigmoidf(go) * tanhf(c);
}

__global__ void flow2_kernel(const float* __restrict__ FHp,
                             const float* __restrict__ fw2,
                             const float* __restrict__ fb2,
                             float* __restrict__ FLOWp,
                             float* __restrict__ out) {
    __shared__ float w[NF * HH];
    int tid = threadIdx.x;
    for (int q = tid; q < NF * HH; q += blockDim.x) w[q] = fw2[q];
    __syncthreads();
    int warp = tid >> 5, lane = tid & 31;
    int b = blockIdx.x * 8 + warp;
    const float* r = FHp + (size_t)b * HH;
    float a0 = 0.f, a1 = 0.f, a2 = 0.f, a3 = 0.f;
    for (int k = lane; k < HH; k += 32) {
        float v = r[k];
        a0 += v * w[k];
        a1 += v * w[HH + k];
        a2 += v * w[2 * HH + k];
        a3 += v * w[3 * HH + k];
    }
#pragma unroll
    for (int off = 16; off; off >>= 1) {
        a0 += __shfl_xor_sync(0xffffffffu, a0, off);
        a1 += __shfl_xor_sync(0xffffffffu, a1, off);
        a2 += __shfl_xor_sync(0xffffffffu, a2, off);
        a3 += __shfl_xor_sync(0xffffffffu, a3, off);
    }
    if (lane == 0) {
        a0 += fb2[0]; a1 += fb2[1]; a2 += fb2[2]; a3 += fb2[3];
        float m = fmaxf(fmaxf(a0, a1), fmaxf(a2, a3));
        float e0 = expf(a0 - m), e1 = expf(a1 - m), e2 = expf(a2 - m), e3 = expf(a3 - m);
        float inv = 1.f / (e0 + e1 + e2 + e3);
        float p0 = e0 * inv, p1 = e1 * inv, p2 = e2 * inv, p3 = e3 * inv;
        FLOWp[b * 4 + 0] = p0; FLOWp[b * 4 + 1] = p1;
        FLOWp[b * 4 + 2] = p2; FLOWp[b * 4 + 3] = p3;
        out[OFF_FLOW + b * 4 + 0] = p0; out[OFF_FLOW + b * 4 + 1] = p1;
        out[OFF_FLOW + b * 4 + 2] = p2; out[OFF_FLOW + b * 4 + 3] = p3;
    }
}

__global__ void build_comb(const float* __restrict__ x,
                           const float* __restrict__ Hs,
                           const float* __restrict__ FLOWp,
                           float* __restrict__ comb) {
    size_t idx = (size_t)blockIdx.x * blockDim.x + threadIdx.x;
    if (idx >= (size_t)BATCH * KCOMB) return;
    int b = (int)(idx / KCOMB), c = (int)(idx % KCOMB);
    float v;
    if (c < DD)            v = x[(size_t)b * DD + c];
    else if (c < DD + HH)  v = Hs[(size_t)b * HH + (c - DD)];
    else                   v = FLOWp[b * 4 + (c - DD - HH)];
    comb[idx] = v;
}

__global__ void final_gate_kernel(const float* __restrict__ adjraw,
                                  const float* __restrict__ flow,
                                  const float* __restrict__ spec,
                                  float* __restrict__ out) {
    __shared__ float s_spec[EE * NF];
    __shared__ float s_usage[EE];
    int tid = threadIdx.x;
    if (tid < EE * NF) s_spec[tid] = spec[tid];
    if (tid < EE)      s_usage[tid] = 0.f;
    __syncthreads();

    int warp = tid >> 5, lane = tid & 31;
    int b = blockIdx.x * 8 + warp;

    float f0 = flow[b * 4 + 0], f1 = flow[b * 4 + 1], f2 = flow[b * 4 + 2], f3 = flow[b * 4 + 3];
    int e0 = lane, e1 = lane + 32;
    float sp0 = 0.1f * (f0 * s_spec[e0 * 4 + 0] + f1 * s_spec[e0 * 4 + 1] +
                        f2 * s_spec[e0 * 4 + 2] + f3 * s_spec[e0 * 4 + 3]);
    float sp1 = 0.1f * (f0 * s_spec[e1 * 4 + 0] + f1 * s_spec[e1 * 4 + 1] +
                        f2 * s_spec[e1 * 4 + 2] + f3 * s_spec[e1 * 4 + 3]);
    float l0 = adjraw[(size_t)b * EE + e0] + sp0;
    float l1 = adjraw[(size_t)b * EE + e1] + sp1;
    out[OFF_ADJ + (size_t)b * EE + e0] = l0;
    out[OFF_ADJ + (size_t)b * EE + e1] = l1;

    float m = fmaxf(l0, l1);
#pragma unroll
    for (int off = 16; off; off >>= 1) m = fmaxf(m, __shfl_xor_sync(0xffffffffu, m, off));
    float x0 = expf(l0 - m), x1 = expf(l1 - m);
    float s = x0 + x1;
#pragma unroll
    for (int off = 16; off; off >>= 1) s += __shfl_xor_sync(0xffffffffu, s, off);
    float inv_s = 1.f / s;
    float p0 = x0 * inv_s, p1 = x1 * inv_s;

    atomicAdd(&s_usage[e0], p0);
    atomicAdd(&s_usage[e1], p1);

    float tp[8]; int ti[8];
    float v0 = p0, v1 = p1;
#pragma unroll
    for (int it = 0; it < 8; it++) {
        float v; int bi;
        if (v1 > v0) { v = v1; bi = e1; } else { v = v0; bi = e0; }
#pragma unroll
        for (int off = 16; off; off >>= 1) {
            float ov = __shfl_xor_sync(0xffffffffu, v, off);
            int   oi = __shfl_xor_sync(0xffffffffu, bi, off);
            if (ov > v || (ov == v && oi < bi)) { v = ov; bi = oi; }
        }
        tp[it] = v; ti[it] = bi;
        if (bi == e0) v0 = -1.f;
        if (bi == e1) v1 = -1.f;
    }
    float ssum = 0.f;
#pragma unroll
    for (int it = 0; it < 8; it++) ssum += tp[it];
    float invn = 1.f / (ssum + 1e-8f);
    if (lane < 8) {
        out[OFF_TOPP + (size_t)b * 8 + lane] = tp[lane] * invn;
        out[OFF_TOPI + (size_t)b * 8 + lane] = (float)ti[lane];
    }
    __syncthreads();
    if (tid < EE) atomicAdd(&out[OFF_USAGE + tid], s_usage[tid]);
}

__global__ void loss_kernel(float* __restrict__ out) {
    __shared__ float red[EE];
    int t = threadIdx.x;  // 64 threads
    float u = out[OFF_USAGE + t] / (float)BATCH;
    out[OFF_USAGE + t] = u;
    red[t] = -(1.0f / 64.f) * log1pf(64.f * u - 1.f);
    __syncthreads();
    for (int s = 32; s; s >>= 1) {
        if (t < s) red[t] += red[t + s];
        __syncthreads();
    }
    if (t == 0) out[OFF_LOSS] = red[0] / 64.f;
}

// ------------------------- launch -------------------------
extern "C" void kernel_launch(void* const* d_in, const int* in_sizes, int n_in,
                              void* d_out, int out_size) {
    const float* x        = (const float*)d_in[0];
    const float* context  = (const float*)d_in[1];
    const float* W_ih     = (const float*)d_in[2];
    const float* W_hh     = (const float*)d_in[3];
    const float* b_ih     = (const float*)d_in[4];
    const float* b_hh     = (const float*)d_in[5];
    const float* fw1      = (const float*)d_in[6];
    const float* fb1      = (const float*)d_in[7];
    const float* fw2      = (const float*)d_in[8];
    const float* fb2      = (const float*)d_in[9];
    const float* gw1      = (const float*)d_in[10];
    const float* gb1      = (const float*)d_in[11];
    const float* gw2      = (const float*)d_in[12];
    const float* gb2      = (const float*)d_in[13];
    const float* espec    = (const float*)d_in[14];
    float* out = (float*)d_out;

    float *XS, *GATES, *Hs, *Cs, *FH, *FLOW, *COMB, *G1, *ADJ, *BSUM;
    cudaGetSymbolAddress((void**)&XS,    d_XS);
    cudaGetSymbolAddress((void**)&GATES, d_GATES);
    cudaGetSymbolAddress((void**)&Hs,    d_Hst);
    cudaGetSymbolAddress((void**)&Cs,    d_Cst);
    cudaGetSymbolAddress((void**)&FH,    d_FH);
    cudaGetSymbolAddress((void**)&FLOW,  d_FLOW);
    cudaGetSymbolAddress((void**)&COMB,  d_COMB);
    cudaGetSymbolAddress((void**)&G1,    d_G1);
    cudaGetSymbolAddress((void**)&ADJ,   d_ADJ);
    cudaGetSymbolAddress((void**)&BSUM,  d_BSUM);

    // smem: 2 stages * (A hi/lo + B hi/lo), 144B row pitch, fp32 tiles
    const int SMEM128 = 2 * (2 * 128 * 144 + 2 * 128 * 144);  // 147456
    const int SMEM64  = 2 * (2 * 128 * 144 + 2 * 64 * 144);   // 110592
    cudaFuncSetAttribute(gemm_mma<128>, cudaFuncAttributeMaxDynamicSharedMemorySize, SMEM128);
    cudaFuncSetAttribute(gemm_mma<64>,  cudaFuncAttributeMaxDynamicSharedMemorySize, SMEM64);

    bias_sum_kernel<<<(G4H + 255) / 256, 256>>>(b_ih, b_hh, BSUM);
    zero_kernel<<<(unsigned)(((size_t)BATCH * HH + 255) / 256), 256>>>(Cs, (size_t)BATCH * HH);

    // XS = context @ W_ih^T + (b_ih + b_hh); rows = (b*T + t)
    gemm_mma<128><<<dim3(G4H / 128, (BATCH * TT) / 128), 512, SMEM128>>>(
        context, DD, W_ih, DD, XS, G4H, DD, BSUM, nullptr, 0, 0);

    // t = 0: gates straight from XS (h0 = 0)
    lstm_pw<<<(BATCH * HH + 255) / 256, 256>>>(XS, TT * G4H, Hs, Cs);

    for (int t = 1; t < TT; t++) {
        gemm_mma<128><<<dim3(G4H / 128, BATCH / 128), 512, SMEM128>>>(
            Hs, HH, W_hh, HH, GATES, G4H, HH, nullptr, XS + (size_t)t * G4H, TT * G4H, 0);
        lstm_pw<<<(BATCH * HH + 255) / 256, 256>>>(GATES, G4H, Hs, Cs);
    }

    // flow hidden: relu(x @ fw1^T + fb1)
    gemm_mma<128><<<dim3(HH / 128, BATCH / 128), 512, SMEM128>>>(
        x, DD, fw1, DD, FH, HH, DD, fb1, nullptr, 0, 1);

    flow2_kernel<<<BATCH / 8, 256>>>(FH, fw2, fb2, FLOW, out);

    build_comb<<<(unsigned)(((size_t)BATCH * KCOMB + 255) / 256), 256>>>(x, Hs, FLOW, COMB);

    // gate hidden: relu(combined @ gw1^T + gb1), K = 1540 (ragged last chunk)
    gemm_mma<128><<<dim3(DD / 128, BATCH / 128), 512, SMEM128>>>(
        COMB, KCOMB, gw1, KCOMB, G1, DD, KCOMB, gb1, nullptr, 0, 1);

    // gate logits: G1 @ gw2^T + gb2
    gemm_mma<64><<<dim3(EE / 64, BATCH / 128), 256, SMEM64>>>(
        G1, DD, gw2, DD, ADJ, EE, DD, gb2, nullptr, 0, 0);

    zero_kernel<<<1, 64>>>(out + OFF_USAGE, EE);
    final_gate_kernel<<<BATCH / 8, 256>>>(ADJ, FLOW, espec, out);
    loss_kernel<<<1, 64>>>(out);
}

// round 10
// speedup vs baseline: 1.1583x; 1.0064x over previous
#include <cuda_runtime.h>
#include <cstdint>
#include <math.h>

#define BATCH 16384
#define TT 7
#define DD 1024
#define HH 512
#define EE 64
#define NF 4
#define G4H 2048              // 4*H
#define KCOMB 1540            // D + H + 4

// Output offsets (float32 concat in reference return order)
#define OFF_TOPP  ((size_t)0)
#define OFF_TOPI  ((size_t)131072)
#define OFF_LOSS  ((size_t)262144)
#define OFF_FLOW  ((size_t)262145)
#define OFF_USAGE ((size_t)327681)
#define OFF_ADJ   ((size_t)327745)

// ------------------------- scratch (static, no allocs) -------------------------
__device__ float d_XS[(size_t)BATCH * TT * G4H];
__device__ float d_GATES[(size_t)BATCH * G4H];
__device__ float d_Hst[(size_t)BATCH * HH];
__device__ float d_Cst[(size_t)BATCH * HH];
__device__ float d_FH[(size_t)BATCH * HH];
__device__ float d_FLOW[(size_t)BATCH * NF];
__device__ float d_COMB[(size_t)BATCH * KCOMB];
__device__ float d_G1[(size_t)BATCH * DD];
__device__ float d_ADJ[(size_t)BATCH * EE];
__device__ float d_BSUM[G4H];

// ------------------------- helpers -------------------------
__device__ __forceinline__ uint32_t smem_u32(const void* p) {
    uint32_t a;
    asm("{ .reg .u64 t; cvta.to.shared.u64 t, %1; cvt.u32.u64 %0, t; }" : "=r"(a) : "l"(p));
    return a;
}
__device__ __forceinline__ void ldsm_x4(uint32_t* r, uint32_t addr) {
    asm volatile("ldmatrix.sync.aligned.m8n8.x4.shared.b16 {%0,%1,%2,%3}, [%4];"
        : "=r"(r[0]), "=r"(r[1]), "=r"(r[2]), "=r"(r[3]) : "r"(addr));
}
// tf32 mma: A 4 regs (m16k8), B 2 regs (k8n8), C 4 f32
__device__ __forceinline__ void mma1688(float* c, const uint32_t* a,
                                        uint32_t b0, uint32_t b1) {
    asm volatile(
        "mma.sync.aligned.m16n8k8.row.col.f32.tf32.tf32.f32 "
        "{%0,%1,%2,%3}, {%4,%5,%6,%7}, {%8,%9}, {%0,%1,%2,%3};"
        : "+f"(c[0]), "+f"(c[1]), "+f"(c[2]), "+f"(c[3])
        : "r"(a[0]), "r"(a[1]), "r"(a[2]), "r"(a[3]), "r"(b0), "r"(b1));
}
__device__ __forceinline__ float tf32_rnd(float v) {
    float r; asm("cvt.rna.tf32.f32 %0, %1;" : "=f"(r) : "f"(v)); return r;
}
// split fp32 -> tf32 hi + tf32 lo (no scaling; tf32 has full fp32 exponent range)
__device__ __forceinline__ void tsplit(float v, float& h, float& l) {
    h = tf32_rnd(v);
    l = tf32_rnd(v - h);
}

// ------------------------- mma.sync 4xTF32 GEMM (product-interleaved) --------
// C[m,n] = sum_k A[m,k]*W[n,k] (+bias[n]) (+addend[m,n]) (relu)
// BM=128, BK=32 fp32-k per chunk; BN in {128, 64}. Warp tile 32x32.
// Inner scheduling: product-major across the 8 warp tiles, so dependent MMAs
// to the same accumulator are 8 instructions apart (hide HMMA latency).
// Per-accumulator summation order is IDENTICAL to the R6 passing kernel
// (hh, hl, lh, ll per k-step) => bit-identical results.
template<int BN>
__global__ void __launch_bounds__(128 * (BN / 32), 1)
gemm_mma(const float* __restrict__ A, int lda,
         const float* __restrict__ W, int ldw,
         float* __restrict__ C, int ldc, int K,
         const float* __restrict__ bias,
         const float* __restrict__ addend, int add_ld,
         int relu)
{
    constexpr int BM = 128, BK = 32;
    constexpr int NW = 4 * (BN / 32);
    constexpr int T = 32 * NW;
    constexpr int PITCHB = 144;             // 32 floats + 4 pad floats (bytes)
    constexpr int A_HALF = BM * PITCHB;     // one A sub-tile (hi or lo)
    constexpr int B_HALF = BN * PITCHB;
    constexpr int STAGE = 2 * A_HALF + 2 * B_HALF;
    constexpr int AV = BM * BK / 4 / T;     // float4 loads/thread for A
    constexpr int BV = BN * BK / 4 / T;

    extern __shared__ char smem[];
    const uint32_t dsm = smem_u32(smem);

    const int tid = threadIdx.x;
    const int lane = tid & 31;
    const int wid = tid >> 5;
    const int wm = (wid & 3) * 32;
    const int wn = (wid >> 2) * 32;
    const long m0 = (long)blockIdx.y * BM;
    const int  n0 = blockIdx.x * BN;

    float Cacc[2][4][4];
#pragma unroll
    for (int i = 0; i < 2; i++)
#pragma unroll
        for (int j = 0; j < 4; j++)
#pragma unroll
            for (int q = 0; q < 4; q++) Cacc[i][j][q] = 0.f;

    float4 ra[AV], rb[BV];

    auto load_chunk = [&](int ch) {
        const int k0 = ch * BK;
#pragma unroll
        for (int q = 0; q < AV; q++) {
            int idx = tid + q * T;
            int row = idx >> 3, c4 = (idx & 7) * 4;
            ra[q] = (k0 + c4 < K)
                ? *reinterpret_cast<const float4*>(A + (m0 + row) * (long)lda + k0 + c4)
                : make_float4(0.f, 0.f, 0.f, 0.f);
        }
#pragma unroll
        for (int q = 0; q < BV; q++) {
            int idx = tid + q * T;
            int row = idx >> 3, c4 = (idx & 7) * 4;
            rb[q] = (k0 + c4 < K)
                ? *reinterpret_cast<const float4*>(W + (long)(n0 + row) * ldw + k0 + c4)
                : make_float4(0.f, 0.f, 0.f, 0.f);
        }
    };

    auto store_chunk = [&](int s) {
        char* aHi = smem + s * STAGE;
        char* aLo = aHi + A_HALF;
        char* bHi = aHi + 2 * A_HALF;
        char* bLo = bHi + B_HALF;
#pragma unroll
        for (int q = 0; q < AV; q++) {
            int idx = tid + q * T;
            int row = idx >> 3, c4 = (idx & 7) * 4;
            int off = row * PITCHB + c4 * 4;
            float4 h, l;
            tsplit(ra[q].x, h.x, l.x); tsplit(ra[q].y, h.y, l.y);
            tsplit(ra[q].z, h.z, l.z); tsplit(ra[q].w, h.w, l.w);
            *reinterpret_cast<float4*>(aHi + off) = h;
            *reinterpret_cast<float4*>(aLo + off) = l;
        }
#pragma unroll
        for (int q = 0; q < BV; q++) {
            int idx = tid + q * T;
            int row = idx >> 3, c4 = (idx & 7) * 4;
            int off = row * PITCHB + c4 * 4;
            float4 h, l;
            tsplit(rb[q].x, h.x, l.x); tsplit(rb[q].y, h.y, l.y);
            tsplit(rb[q].z, h.z, l.z); tsplit(rb[q].w, h.w, l.w);
            *reinterpret_cast<float4*>(bHi + off) = h;
            *reinterpret_cast<float4*>(bLo + off) = l;
        }
    };

    // ldmatrix per-lane offsets (byte gathers over fp32 tiles)
    const uint32_t a_l_off = (uint32_t)((lane & 15) * PITCHB + (lane >> 4) * 16);
    const uint32_t b_l_off = (uint32_t)((((lane >> 3) & 1) * 8 + (lane & 7)) * PITCHB
                                        + (lane >> 4) * 16);

    auto compute = [&](int s) {
        const uint32_t base = dsm + s * STAGE;
        const uint32_t aH = base + (uint32_t)(wm * PITCHB) + a_l_off;
        const uint32_t bH = base + 2 * A_HALF + (uint32_t)(wn * PITCHB) + b_l_off;
#pragma unroll
        for (int ks = 0; ks < 4; ks++) {
            uint32_t ah[2][4], al[2][4];
            uint32_t bh[4][2], bl[4][2];
#pragma unroll
            for (int mi = 0; mi < 2; mi++) {
                uint32_t ad = aH + mi * 16 * PITCHB + ks * 32;
                ldsm_x4(ah[mi], ad);
                ldsm_x4(al[mi], ad + A_HALF);
            }
#pragma unroll
            for (int p = 0; p < 2; p++) {
                uint32_t bd = bH + p * 16 * PITCHB + ks * 32;
                uint32_t t[4];
                ldsm_x4(t, bd);
                bh[2*p][0] = t[0]; bh[2*p][1] = t[2];
                bh[2*p+1][0] = t[1]; bh[2*p+1][1] = t[3];
                ldsm_x4(t, bd + B_HALF);
                bl[2*p][0] = t[0]; bl[2*p][1] = t[2];
                bl[2*p+1][0] = t[1]; bl[2*p+1][1] = t[3];
            }
            // product-major interleave: dependent MMAs 8 apart, per-tile
            // accumulation order unchanged (hh, hl, lh, ll).
#pragma unroll
            for (int mi = 0; mi < 2; mi++)
#pragma unroll
                for (int ni = 0; ni < 4; ni++)
                    mma1688(Cacc[mi][ni], ah[mi], bh[ni][0], bh[ni][1]);
#pragma unroll
            for (int mi = 0; mi < 2; mi++)
#pragma unroll
                for (int ni = 0; ni < 4; ni++)
                    mma1688(Cacc[mi][ni], ah[mi], bl[ni][0], bl[ni][1]);
#pragma unroll
            for (int mi = 0; mi < 2; mi++)
#pragma unroll
                for (int ni = 0; ni < 4; ni++)
                    mma1688(Cacc[mi][ni], al[mi], bh[ni][0], bh[ni][1]);
#pragma unroll
            for (int mi = 0; mi < 2; mi++)
#pragma unroll
                for (int ni = 0; ni < 4; ni++)
                    mma1688(Cacc[mi][ni], al[mi], bl[ni][0], bl[ni][1]);
        }
    };

    const int nch = (K + BK - 1) / BK;

    load_chunk(0);
    store_chunk(0);
    __syncthreads();

    for (int i = 0; i < nch; i++) {
        const int s = i & 1;
        if (i + 1 < nch) load_chunk(i + 1);
        compute(s);
        if (i + 1 < nch) {
            store_chunk(s ^ 1);
            __syncthreads();
        }
    }

    // epilogue (+bias)(+addend)(relu)
#pragma unroll
    for (int mi = 0; mi < 2; mi++)
#pragma unroll
        for (int ni = 0; ni < 4; ni++)
#pragma unroll
            for (int h = 0; h < 2; h++) {
                long row = m0 + wm + mi * 16 + (lane >> 2) + h * 8;
                int  col = n0 + wn + ni * 8 + (lane & 3) * 2;
                float v0 = Cacc[mi][ni][2 * h + 0];
                float v1 = Cacc[mi][ni][2 * h + 1];
                if (bias) { v0 += bias[col]; v1 += bias[col + 1]; }
                if (addend) {
                    float2 ad = *reinterpret_cast<const float2*>(addend + row * (long)add_ld + col);
                    v0 += ad.x; v1 += ad.y;
                }
                if (relu) { v0 = fmaxf(v0, 0.f); v1 = fmaxf(v1, 0.f); }
                *reinterpret_cast<float2*>(C + row * (long)ldc + col) = make_float2(v0, v1);
            }
}

// ------------------------- small kernels -------------------------
__global__ void bias_sum_kernel(const float* __restrict__ b_ih,
                                const float* __restrict__ b_hh,
                                float* __restrict__ bsum) {
    int i = blockIdx.x * blockDim.x + threadIdx.x;
    if (i < G4H) bsum[i] = b_ih[i] + b_hh[i];
}

__global__ void zero_kernel(float* __restrict__ p, size_t n) {
    size_t i = (size_t)blockIdx.x * blockDim.x + threadIdx.x;
    if (i < n) p[i] = 0.f;
}

__device__ __forceinline__ float sigmoidf(float x) { return 1.f / (1.f + expf(-x)); }

__global__ void lstm_pw(const float* __restrict__ gates, int rstride,
                        float* __restrict__ Hs, float* __restrict__ Cs) {
    int idx = blockIdx.x * blockDim.x + threadIdx.x;
    if (idx >= BATCH * HH) return;
    int b = idx / HH, j = idx % HH;
    const float* g = gates + (size_t)b * rstride;
    float gi = g[j], gf = g[HH + j], gg = g[2 * HH + j], go = g[3 * HH + j];
    float c = sigmoidf(gf) * Cs[idx] + sigmoidf(gi) * tanhf(gg);
    Cs[idx] = c;
    Hs[idx] = sigmoidf(go) * tanhf(c);
}

__global__ void flow2_kernel(const float* __restrict__ FHp,
                             const float* __restrict__ fw2,
                             const float* __restrict__ fb2,
                             float* __restrict__ FLOWp,
                             float* __restrict__ out) {
    __shared__ float w[NF * HH];
    int tid = threadIdx.x;
    for (int q = tid; q < NF * HH; q += blockDim.x) w[q] = fw2[q];
    __syncthreads();
    int warp = tid >> 5, lane = tid & 31;
    int b = blockIdx.x * 8 + warp;
    const float* r = FHp + (size_t)b * HH;
    float a0 = 0.f, a1 = 0.f, a2 = 0.f, a3 = 0.f;
    for (int k = lane; k < HH; k += 32) {
        float v = r[k];
        a0 += v * w[k];
        a1 += v * w[HH + k];
        a2 += v * w[2 * HH + k];
        a3 += v * w[3 * HH + k];
    }
#pragma unroll
    for (int off = 16; off; off >>= 1) {
        a0 += __shfl_xor_sync(0xffffffffu, a0, off);
        a1 += __shfl_xor_sync(0xffffffffu, a1, off);
        a2 += __shfl_xor_sync(0xffffffffu, a2, off);
        a3 += __shfl_xor_sync(0xffffffffu, a3, off);
    }
    if (lane == 0) {
        a0 += fb2[0]; a1 += fb2[1]; a2 += fb2[2]; a3 += fb2[3];
        float m = fmaxf(fmaxf(a0, a1), fmaxf(a2, a3));
        float e0 = expf(a0 - m), e1 = expf(a1 - m), e2 = expf(a2 - m), e3 = expf(a3 - m);
        float inv = 1.f / (e0 + e1 + e2 + e3);
        float p0 = e0 * inv, p1 = e1 * inv, p2 = e2 * inv, p3 = e3 * inv;
        FLOWp[b * 4 + 0] = p0; FLOWp[b * 4 + 1] = p1;
        FLOWp[b * 4 + 2] = p2; FLOWp[b * 4 + 3] = p3;
        out[OFF_FLOW + b * 4 + 0] = p0; out[OFF_FLOW + b * 4 + 1] = p1;
        out[OFF_FLOW + b * 4 + 2] = p2; out[OFF_FLOW + b * 4 + 3] = p3;
    }
}

__global__ void build_comb(const float* __restrict__ x,
                           const float* __restrict__ Hs,
                           const float* __restrict__ FLOWp,
                           float* __restrict__ comb) {
    size_t idx = (size_t)blockIdx.x * blockDim.x + threadIdx.x;
    if (idx >= (size_t)BATCH * KCOMB) return;
    int b = (int)(idx / KCOMB), c = (int)(idx % KCOMB);
    float v;
    if (c < DD)            v = x[(size_t)b * DD + c];
    else if (c < DD + HH)  v = Hs[(size_t)b * HH + (c - DD)];
    else                   v = FLOWp[b * 4 + (c - DD - HH)];
    comb[idx] = v;
}

__global__ void final_gate_kernel(const float* __restrict__ adjraw,
                                  const float* __restrict__ flow,
                                  const float* __restrict__ spec,
                                  float* __restrict__ out) {
    __shared__ float s_spec[EE * NF];
    __shared__ float s_usage[EE];
    int tid = threadIdx.x;
    if (tid < EE * NF) s_spec[tid] = spec[tid];
    if (tid < EE)      s_usage[tid] = 0.f;
    __syncthreads();

    int warp = tid >> 5, lane = tid & 31;
    int b = blockIdx.x * 8 + warp;

    float f0 = flow[b * 4 + 0], f1 = flow[b * 4 + 1], f2 = flow[b * 4 + 2], f3 = flow[b * 4 + 3];
    int e0 = lane, e1 = lane + 32;
    float sp0 = 0.1f * (f0 * s_spec[e0 * 4 + 0] + f1 * s_spec[e0 * 4 + 1] +
                        f2 * s_spec[e0 * 4 + 2] + f3 * s_spec[e0 * 4 + 3]);
    float sp1 = 0.1f * (f0 * s_spec[e1 * 4 + 0] + f1 * s_spec[e1 * 4 + 1] +
                        f2 * s_spec[e1 * 4 + 2] + f3 * s_spec[e1 * 4 + 3]);
    float l0 = adjraw[(size_t)b * EE + e0] + sp0;
    float l1 = adjraw[(size_t)b * EE + e1] + sp1;
    out[OFF_ADJ + (size_t)b * EE + e0] = l0;
    out[OFF_ADJ + (size_t)b * EE + e1] = l1;

    float m = fmaxf(l0, l1);
#pragma unroll
    for (int off = 16; off; off >>= 1) m = fmaxf(m, __shfl_xor_sync(0xffffffffu, m, off));
    float x0 = expf(l0 - m), x1 = expf(l1 - m);
    float s = x0 + x1;
#pragma unroll
    for (int off = 16; off; off >>= 1) s += __shfl_xor_sync(0xffffffffu, s, off);
    float inv_s = 1.f / s;
    float p0 = x0 * inv_s, p1 = x1 * inv_s;

    atomicAdd(&s_usage[e0], p0);
    atomicAdd(&s_usage[e1], p1);

    float tp[8]; int ti[8];
    float v0 = p0, v1 = p1;
#pragma unroll
    for (int it = 0; it < 8; it++) {
        float v; int bi;
        if (v1 > v0) { v = v1; bi = e1; } else { v = v0; bi = e0; }
#pragma unroll
        for (int off = 16; off; off >>= 1) {
            float ov = __shfl_xor_sync(0xffffffffu, v, off);
            int   oi = __shfl_xor_sync(0xffffffffu, bi, off);
            if (ov > v || (ov == v && oi < bi)) { v = ov; bi = oi; }
        }
        tp[it] = v; ti[it] = bi;
        if (bi == e0) v0 = -1.f;
        if (bi == e1) v1 = -1.f;
    }
    float ssum = 0.f;
#pragma unroll
    for (int it = 0; it < 8; it++) ssum += tp[it];
    float invn = 1.f / (ssum + 1e-8f);
    if (lane < 8) {
        out[OFF_TOPP + (size_t)b * 8 + lane] = tp[lane] * invn;
        out[OFF_TOPI + (size_t)b * 8 + lane] = (float)ti[lane];
    }
    __syncthreads();
    if (tid < EE) atomicAdd(&out[OFF_USAGE + tid], s_usage[tid]);
}

__global__ void loss_kernel(float* __restrict__ out) {
    __shared__ float red[EE];
    int t = threadIdx.x;  // 64 threads
    float u = out[OFF_USAGE + t] / (float)BATCH;
    out[OFF_USAGE + t] = u;
    red[t] = -(1.0f / 64.f) * log1pf(64.f * u - 1.f);
    __syncthreads();
    for (int s = 32; s; s >>= 1) {
        if (t < s) red[t] += red[t + s];
        __syncthreads();
    }
    if (t == 0) out[OFF_LOSS] = red[0] / 64.f;
}

// ------------------------- launch -------------------------
extern "C" void kernel_launch(void* const* d_in, const int* in_sizes, int n_in,
                              void* d_out, int out_size) {
    const float* x        = (const float*)d_in[0];
    const float* context  = (const float*)d_in[1];
    const float* W_ih     = (const float*)d_in[2];
    const float* W_hh     = (const float*)d_in[3];
    const float* b_ih     = (const float*)d_in[4];
    const float* b_hh     = (const float*)d_in[5];
    const float* fw1      = (const float*)d_in[6];
    const float* fb1      = (const float*)d_in[7];
    const float* fw2      = (const float*)d_in[8];
    const float* fb2      = (const float*)d_in[9];
    const float* gw1      = (const float*)d_in[10];
    const float* gb1      = (const float*)d_in[11];
    const float* gw2      = (const float*)d_in[12];
    const float* gb2      = (const float*)d_in[13];
    const float* espec    = (const float*)d_in[14];
    float* out = (float*)d_out;

    float *XS, *GATES, *Hs, *Cs, *FH, *FLOW, *COMB, *G1, *ADJ, *BSUM;
    cudaGetSymbolAddress((void**)&XS,    d_XS);
    cudaGetSymbolAddress((void**)&GATES, d_GATES);
    cudaGetSymbolAddress((void**)&Hs,    d_Hst);
    cudaGetSymbolAddress((void**)&Cs,    d_Cst);
    cudaGetSymbolAddress((void**)&FH,    d_FH);
    cudaGetSymbolAddress((void**)&FLOW,  d_FLOW);
    cudaGetSymbolAddress((void**)&COMB,  d_COMB);
    cudaGetSymbolAddress((void**)&G1,    d_G1);
    cudaGetSymbolAddress((void**)&ADJ,   d_ADJ);
    cudaGetSymbolAddress((void**)&BSUM,  d_BSUM);

    // smem: 2 stages * (A hi/lo + B hi/lo), 144B row pitch, fp32 tiles
    const int SMEM128 = 2 * (2 * 128 * 144 + 2 * 128 * 144);  // 147456
    const int SMEM64  = 2 * (2 * 128 * 144 + 2 * 64 * 144);   // 110592
    cudaFuncSetAttribute(gemm_mma<128>, cudaFuncAttributeMaxDynamicSharedMemorySize, SMEM128);
    cudaFuncSetAttribute(gemm_mma<64>,  cudaFuncAttributeMaxDynamicSharedMemorySize, SMEM64);

    bias_sum_kernel<<<(G4H + 255) / 256, 256>>>(b_ih, b_hh, BSUM);
    zero_kernel<<<(unsigned)(((size_t)BATCH * HH + 255) / 256), 256>>>(Cs, (size_t)BATCH * HH);

    // XS = context @ W_ih^T + (b_ih + b_hh); rows = (b*T + t)
    gemm_mma<128><<<dim3(G4H / 128, (BATCH * TT) / 128), 512, SMEM128>>>(
        context, DD, W_ih, DD, XS, G4H, DD, BSUM, nullptr, 0, 0);

    // t = 0: gates straight from XS (h0 = 0)
    lstm_pw<<<(BATCH * HH + 255) / 256, 256>>>(XS, TT * G4H, Hs, Cs);

    for (int t = 1; t < TT; t++) {
        gemm_mma<128><<<dim3(G4H / 128, BATCH / 128), 512, SMEM128>>>(
            Hs, HH, W_hh, HH, GATES, G4H, HH, nullptr, XS + (size_t)t * G4H, TT * G4H, 0);
        lstm_pw<<<(BATCH * HH + 255) / 256, 256>>>(GATES, G4H, Hs, Cs);
    }

    // flow hidden: relu(x @ fw1^T + fb1)
    gemm_mma<128><<<dim3(HH / 128, BATCH / 128), 512, SMEM128>>>(
        x, DD, fw1, DD, FH, HH, DD, fb1, nullptr, 0, 1);

    flow2_kernel<<<BATCH / 8, 256>>>(FH, fw2, fb2, FLOW, out);

    build_comb<<<(unsigned)(((size_t)BATCH * KCOMB + 255) / 256), 256>>>(x, Hs, FLOW, COMB);

    // gate hidden: relu(combined @ gw1^T + gb1), K = 1540 (ragged last chunk)
    gemm_mma<128><<<dim3(DD / 128, BATCH / 128), 512, SMEM128>>>(
        COMB, KCOMB, gw1, KCOMB, G1, DD, KCOMB, gb1, nullptr, 0, 1);

    // gate logits: G1 @ gw2^T + gb2
    gemm_mma<64><<<dim3(EE / 64, BATCH / 128), 256, SMEM64>>>(
        G1, DD, gw2, DD, ADJ, EE, DD, gb2, nullptr, 0, 0);

    zero_kernel<<<1, 64>>>(out + OFF_USAGE, EE);
    final_gate_kernel<<<BATCH / 8, 256>>>(ADJ, FLOW, espec, out);
    loss_kernel<<<1, 64>>>(out);
}

// round 12
// speedup vs baseline: 1.4355x; 1.2393x over previous
#include <cuda_runtime.h>
#include <cstdint>
#include <math.h>

#define BATCH 16384
#define TT 7
#define DD 1024
#define HH 512
#define EE 64
#define NF 4
#define G4H 2048              // 4*H
#define KCOMB 1540            // D + H + 4

// Output offsets (float32 concat in reference return order)
#define OFF_TOPP  ((size_t)0)
#define OFF_TOPI  ((size_t)131072)
#define OFF_LOSS  ((size_t)262144)
#define OFF_FLOW  ((size_t)262145)
#define OFF_USAGE ((size_t)327681)
#define OFF_ADJ   ((size_t)327745)

// ------------------------- scratch (static, no allocs) -------------------------
__device__ float d_XS[(size_t)BATCH * TT * G4H];
__device__ float d_GATES[(size_t)BATCH * G4H];
__device__ float d_Hst[(size_t)BATCH * HH];
__device__ float d_Cst[(size_t)BATCH * HH];
__device__ float d_FH[(size_t)BATCH * HH];
__device__ float d_FLOW[(size_t)BATCH * NF];
__device__ float d_COMB[(size_t)BATCH * KCOMB];
__device__ float d_G1[(size_t)BATCH * DD];
__device__ float d_ADJ[(size_t)BATCH * EE];

// ------------------------- helpers -------------------------
__device__ __forceinline__ uint32_t smem_u32(const void* p) {
    uint32_t a;
    asm("{ .reg .u64 t; cvta.to.shared.u64 t, %1; cvt.u32.u64 %0, t; }" : "=r"(a) : "l"(p));
    return a;
}
__device__ __forceinline__ void ldsm_x4(uint32_t* r, uint32_t addr) {
    asm volatile("ldmatrix.sync.aligned.m8n8.x4.shared.b16 {%0,%1,%2,%3}, [%4];"
        : "=r"(r[0]), "=r"(r[1]), "=r"(r[2]), "=r"(r[3]) : "r"(addr));
}
// tf32 mma: A 4 regs (m16k8), B 2 regs (k8n8), C 4 f32
__device__ __forceinline__ void mma1688(float* c, const uint32_t* a,
                                        uint32_t b0, uint32_t b1) {
    asm volatile(
        "mma.sync.aligned.m16n8k8.row.col.f32.tf32.tf32.f32 "
        "{%0,%1,%2,%3}, {%4,%5,%6,%7}, {%8,%9}, {%0,%1,%2,%3};"
        : "+f"(c[0]), "+f"(c[1]), "+f"(c[2]), "+f"(c[3])
        : "r"(a[0]), "r"(a[1]), "r"(a[2]), "r"(a[3]), "r"(b0), "r"(b1));
}
__device__ __forceinline__ float tf32_rnd(float v) {
    float r; asm("cvt.rna.tf32.f32 %0, %1;" : "=f"(r) : "f"(v)); return r;
}
// split fp32 -> tf32 hi + tf32 lo (no scaling; tf32 has full fp32 exponent range)
__device__ __forceinline__ void tsplit(float v, float& h, float& l) {
    h = tf32_rnd(v);
    l = tf32_rnd(v - h);
}

// ------------------------- mma.sync 3xTF32 GEMM (product-interleaved) --------
// C[m,n] = sum_k A[m,k]*W[n,k] (+bias[n]) (+bias2[n]) (+addend[m,n]) (relu)
// BM=128, BK=32 fp32-k per chunk; BN in {128, 64}. Warp tile 32x32.
// Products: hh + hl + lh (ll dropped; ~1e-7 absolute perturbation).
template<int BN>
__global__ void __launch_bounds__(128 * (BN / 32), 1)
gemm_mma(const float* __restrict__ A, int lda,
         const float* __restrict__ W, int ldw,
         float* __restrict__ C, int ldc, int K,
         const float* __restrict__ bias,
         const float* __restrict__ bias2,
         const float* __restrict__ addend, int add_ld,
         int relu)
{
    constexpr int BM = 128, BK = 32;
    constexpr int NW = 4 * (BN / 32);
    constexpr int T = 32 * NW;
    constexpr int PITCHB = 144;             // 32 floats + 4 pad floats (bytes)
    constexpr int A_HALF = BM * PITCHB;     // one A sub-tile (hi or lo)
    constexpr int B_HALF = BN * PITCHB;
    constexpr int STAGE = 2 * A_HALF + 2 * B_HALF;
    constexpr int AV = BM * BK / 4 / T;     // float4 loads/thread for A
    constexpr int BV = BN * BK / 4 / T;

    extern __shared__ char smem[];
    const uint32_t dsm = smem_u32(smem);

    const int tid = threadIdx.x;
    const int lane = tid & 31;
    const int wid = tid >> 5;
    const int wm = (wid & 3) * 32;
    const int wn = (wid >> 2) * 32;
    const long m0 = (long)blockIdx.y * BM;
    const int  n0 = blockIdx.x * BN;

    float Cacc[2][4][4];
#pragma unroll
    for (int i = 0; i < 2; i++)
#pragma unroll
        for (int j = 0; j < 4; j++)
#pragma unroll
            for (int q = 0; q < 4; q++) Cacc[i][j][q] = 0.f;

    float4 ra[AV], rb[BV];

    auto load_chunk = [&](int ch) {
        const int k0 = ch * BK;
#pragma unroll
        for (int q = 0; q < AV; q++) {
            int idx = tid + q * T;
            int row = idx >> 3, c4 = (idx & 7) * 4;
            ra[q] = (k0 + c4 < K)
                ? *reinterpret_cast<const float4*>(A + (m0 + row) * (long)lda + k0 + c4)
                : make_float4(0.f, 0.f, 0.f, 0.f);
        }
#pragma unroll
        for (int q = 0; q < BV; q++) {
            int idx = tid + q * T;
            int row = idx >> 3, c4 = (idx & 7) * 4;
            rb[q] = (k0 + c4 < K)
                ? *reinterpret_cast<const float4*>(W + (long)(n0 + row) * ldw + k0 + c4)
                : make_float4(0.f, 0.f, 0.f, 0.f);
        }
    };

    auto store_chunk = [&](int s) {
        char* aHi = smem + s * STAGE;
        char* aLo = aHi + A_HALF;
        char* bHi = aHi + 2 * A_HALF;
        char* bLo = bHi + B_HALF;
#pragma unroll
        for (int q = 0; q < AV; q++) {
            int idx = tid + q * T;
            int row = idx >> 3, c4 = (idx & 7) * 4;
            int off = row * PITCHB + c4 * 4;
            float4 h, l;
            tsplit(ra[q].x, h.x, l.x); tsplit(ra[q].y, h.y, l.y);
            tsplit(ra[q].z, h.z, l.z); tsplit(ra[q].w, h.w, l.w);
            *reinterpret_cast<float4*>(aHi + off) = h;
            *reinterpret_cast<float4*>(aLo + off) = l;
        }
#pragma unroll
        for (int q = 0; q < BV; q++) {
            int idx = tid + q * T;
            int row = idx >> 3, c4 = (idx & 7) * 4;
            int off = row * PITCHB + c4 * 4;
            float4 h, l;
            tsplit(rb[q].x, h.x, l.x); tsplit(rb[q].y, h.y, l.y);
            tsplit(rb[q].z, h.z, l.z); tsplit(rb[q].w, h.w, l.w);
            *reinterpret_cast<float4*>(bHi + off) = h;
            *reinterpret_cast<float4*>(bLo + off) = l;
        }
    };

    // ldmatrix per-lane offsets (byte gathers over fp32 tiles)
    const uint32_t a_l_off = (uint32_t)((lane & 15) * PITCHB + (lane >> 4) * 16);
    const uint32_t b_l_off = (uint32_t)((((lane >> 3) & 1) * 8 + (lane & 7)) * PITCHB
                                        + (lane >> 4) * 16);

    auto compute = [&](int s) {
        const uint32_t base = dsm + s * STAGE;
        const uint32_t aH = base + (uint32_t)(wm * PITCHB) + a_l_off;
        const uint32_t bH = base + 2 * A_HALF + (uint32_t)(wn * PITCHB) + b_l_off;
#pragma unroll
        for (int ks = 0; ks < 4; ks++) {
            uint32_t ah[2][4], al[2][4];
            uint32_t bh[4][2], bl[4][2];
#pragma unroll
            for (int mi = 0; mi < 2; mi++) {
                uint32_t ad = aH + mi * 16 * PITCHB + ks * 32;
                ldsm_x4(ah[mi], ad);
                ldsm_x4(al[mi], ad + A_HALF);
            }
#pragma unroll
            for (int p = 0; p < 2; p++) {
                uint32_t bd = bH + p * 16 * PITCHB + ks * 32;
                uint32_t t[4];
                ldsm_x4(t, bd);
                bh[2*p][0] = t[0]; bh[2*p][1] = t[2];
                bh[2*p+1][0] = t[1]; bh[2*p+1][1] = t[3];
                ldsm_x4(t, bd + B_HALF);
                bl[2*p][0] = t[0]; bl[2*p][1] = t[2];
                bl[2*p+1][0] = t[1]; bl[2*p+1][1] = t[3];
            }
            // product-major interleave; per-tile order hh, hl, lh
#pragma unroll
            for (int mi = 0; mi < 2; mi++)
#pragma unroll
                for (int ni = 0; ni < 4; ni++)
                    mma1688(Cacc[mi][ni], ah[mi], bh[ni][0], bh[ni][1]);
#pragma unroll
            for (int mi = 0; mi < 2; mi++)
#pragma unroll
                for (int ni = 0; ni < 4; ni++)
                    mma1688(Cacc[mi][ni], ah[mi], bl[ni][0], bl[ni][1]);
#pragma unroll
            for (int mi = 0; mi < 2; mi++)
#pragma unroll
                for (int ni = 0; ni < 4; ni++)
                    mma1688(Cacc[mi][ni], al[mi], bh[ni][0], bh[ni][1]);
        }
    };

    const int nch = (K + BK - 1) / BK;

    load_chunk(0);
    store_chunk(0);
    __syncthreads();

    for (int i = 0; i < nch; i++) {
        const int s = i & 1;
        if (i + 1 < nch) load_chunk(i + 1);
        compute(s);
        if (i + 1 < nch) {
            store_chunk(s ^ 1);
            __syncthreads();
        }
    }

    // epilogue (+bias)(+bias2)(+addend)(relu)
#pragma unroll
    for (int mi = 0; mi < 2; mi++)
#pragma unroll
        for (int ni = 0; ni < 4; ni++)
#pragma unroll
            for (int h = 0; h < 2; h++) {
                long row = m0 + wm + mi * 16 + (lane >> 2) + h * 8;
                int  col = n0 + wn + ni * 8 + (lane & 3) * 2;
                float v0 = Cacc[mi][ni][2 * h + 0];
                float v1 = Cacc[mi][ni][2 * h + 1];
                if (bias)  { v0 += bias[col];  v1 += bias[col + 1]; }
                if (bias2) { v0 += bias2[col]; v1 += bias2[col + 1]; }
                if (addend) {
                    float2 ad = *reinterpret_cast<const float2*>(addend + row * (long)add_ld + col);
                    v0 += ad.x; v1 += ad.y;
                }
                if (relu) { v0 = fmaxf(v0, 0.f); v1 = fmaxf(v1, 0.f); }
                *reinterpret_cast<float2*>(C + row * (long)ldc + col) = make_float2(v0, v1);
            }
}

// ------------------------- small kernels -------------------------
__global__ void zero_kernel(float* __restrict__ p, size_t n) {
    size_t i = (size_t)blockIdx.x * blockDim.x + threadIdx.x;
    if (i < n) p[i] = 0.f;
}

__device__ __forceinline__ float sigmoidf(float x) { return 1.f / (1.f + expf(-x)); }

__global__ void lstm_pw(const float* __restrict__ gates, int rstride,
                        float* __restrict__ Hs, float* __restrict__ Cs) {
    int idx = blockIdx.x * blockDim.x + threadIdx.x;
    if (idx >= BATCH * HH) return;
    int b = idx / HH, j = idx % HH;
    const float* g = gates + (size_t)b * rstride;
    float gi = g[j], gf = g[HH + j], gg = g[2 * HH + j], go = g[3 * HH + j];
    float c = sigmoidf(gf) * Cs[idx] + sigmoidf(gi) * tanhf(gg);
    Cs[idx] = c;
    Hs[idx] = sigmoidf(go) * tanhf(c);
}

__global__ void flow2_kernel(const float* __restrict__ FHp,
                             const float* __restrict__ fw2,
                             const float* __restrict__ fb2,
                             float* __restrict__ FLOWp,
                             float* __restrict__ out) {
    __shared__ float w[NF * HH];
    int tid = threadIdx.x;
    for (int q = tid; q < NF * HH; q += blockDim.x) w[q] = fw2[q];
    __syncthreads();
    int warp = tid >> 5, lane = tid & 31;
    int b = blockIdx.x * 8 + warp;
    const float* r = FHp + (size_t)b * HH;
    float a0 = 0.f, a1 = 0.f, a2 = 0.f, a3 = 0.f;
    for (int k = lane; k < HH; k += 32) {
        float v = r[k];
        a0 += v * w[k];
        a1 += v * w[HH + k];
        a2 += v * w[2 * HH + k];
        a3 += v * w[3 * HH + k];
    }
#pragma unroll
    for (int off = 16; off; off >>= 1) {
        a0 += __shfl_xor_sync(0xffffffffu, a0, off);
        a1 += __shfl_xor_sync(0xffffffffu, a1, off);
        a2 += __shfl_xor_sync(0xffffffffu, a2, off);
        a3 += __shfl_xor_sync(0xffffffffu, a3, off);
    }
    if (lane == 0) {
        a0 += fb2[0]; a1 += fb2[1]; a2 += fb2[2]; a3 += fb2[3];
        float m = fmaxf(fmaxf(a0, a1), fmaxf(a2, a3));
        float e0 = expf(a0 - m), e1 = expf(a1 - m), e2 = expf(a2 - m), e3 = expf(a3 - m);
        float inv = 1.f / (e0 + e1 + e2 + e3);
        float p0 = e0 * inv, p1 = e1 * inv, p2 = e2 * inv, p3 = e3 * inv;
        FLOWp[b * 4 + 0] = p0; FLOWp[b * 4 + 1] = p1;
        FLOWp[b * 4 + 2] = p2; FLOWp[b * 4 + 3] = p3;
        out[OFF_FLOW + b * 4 + 0] = p0; out[OFF_FLOW + b * 4 + 1] = p1;
        out[OFF_FLOW + b * 4 + 2] = p2; out[OFF_FLOW + b * 4 + 3] = p3;
    }
}

__global__ void build_comb(const float* __restrict__ x,
                           const float* __restrict__ Hs,
                           const float* __restrict__ FLOWp,
                           float* __restrict__ comb) {
    size_t idx = (size_t)blockIdx.x * blockDim.x + threadIdx.x;
    if (idx >= (size_t)BATCH * KCOMB) return;
    int b = (int)(idx / KCOMB), c = (int)(idx % KCOMB);
    float v;
    if (c < DD)            v = x[(size_t)b * DD + c];
    else if (c < DD + HH)  v = Hs[(size_t)b * HH + (c - DD)];
    else                   v = FLOWp[b * 4 + (c - DD - HH)];
    comb[idx] = v;
}

__global__ void final_gate_kernel(const float* __restrict__ adjraw,
                                  const float* __restrict__ flow,
                                  const float* __restrict__ spec,
                                  float* __restrict__ out) {
    __shared__ float s_spec[EE * NF];
    __shared__ float s_usage[EE];
    int tid = threadIdx.x;
    if (tid < EE * NF) s_spec[tid] = spec[tid];
    if (tid < EE)      s_usage[tid] = 0.f;
    __syncthreads();

    int warp = tid >> 5, lane = tid & 31;
    int b = blockIdx.x * 8 + warp;

    float f0 = flow[b * 4 + 0], f1 = flow[b * 4 + 1], f2 = flow[b * 4 + 2], f3 = flow[b * 4 + 3];
    int e0 = lane, e1 = lane + 32;
    float sp0 = 0.1f * (f0 * s_spec[e0 * 4 + 0] + f1 * s_spec[e0 * 4 + 1] +
                        f2 * s_spec[e0 * 4 + 2] + f3 * s_spec[e0 * 4 + 3]);
    float sp1 = 0.1f * (f0 * s_spec[e1 * 4 + 0] + f1 * s_spec[e1 * 4 + 1] +
                        f2 * s_spec[e1 * 4 + 2] + f3 * s_spec[e1 * 4 + 3]);
    float l0 = adjraw[(size_t)b * EE + e0] + sp0;
    float l1 = adjraw[(size_t)b * EE + e1] + sp1;
    out[OFF_ADJ + (size_t)b * EE + e0] = l0;
    out[OFF_ADJ + (size_t)b * EE + e1] = l1;

    float m = fmaxf(l0, l1);
#pragma unroll
    for (int off = 16; off; off >>= 1) m = fmaxf(m, __shfl_xor_sync(0xffffffffu, m, off));
    float x0 = expf(l0 - m), x1 = expf(l1 - m);
    float s = x0 + x1;
#pragma unroll
    for (int off = 16; off; off >>= 1) s += __shfl_xor_sync(0xffffffffu, s, off);
    float inv_s = 1.f / s;
    float p0 = x0 * inv_s, p1 = x1 * inv_s;

    atomicAdd(&s_usage[e0], p0);
    atomicAdd(&s_usage[e1], p1);

    float tp[8]; int ti[8];
    float v0 = p0, v1 = p1;
#pragma unroll
    for (int it = 0; it < 8; it++) {
        float v; int bi;
        if (v1 > v0) { v = v1; bi = e1; } else { v = v0; bi = e0; }
#pragma unroll
        for (int off = 16; off; off >>= 1) {
            float ov = __shfl_xor_sync(0xffffffffu, v, off);
            int   oi = __shfl_xor_sync(0xffffffffu, bi, off);
            if (ov > v || (ov == v && oi < bi)) { v = ov; bi = oi; }
        }
        tp[it] = v; ti[it] = bi;
        if (bi == e0) v0 = -1.f;
        if (bi == e1) v1 = -1.f;
    }
    float ssum = 0.f;
#pragma unroll
    for (int it = 0; it < 8; it++) ssum += tp[it];
    float invn = 1.f / (ssum + 1e-8f);
    if (lane < 8) {
        out[OFF_TOPP + (size_t)b * 8 + lane] = tp[lane] * invn;
        out[OFF_TOPI + (size_t)b * 8 + lane] = (float)ti[lane];
    }
    __syncthreads();
    if (tid < EE) atomicAdd(&out[OFF_USAGE + tid], s_usage[tid]);
}

__global__ void loss_kernel(float* __restrict__ out) {
    __shared__ float red[EE];
    int t = threadIdx.x;  // 64 threads
    float u = out[OFF_USAGE + t] / (float)BATCH;
    out[OFF_USAGE + t] = u;
    red[t] = -(1.0f / 64.f) * log1pf(64.f * u - 1.f);
    __syncthreads();
    for (int s = 32; s; s >>= 1) {
        if (t < s) red[t] += red[t + s];
        __syncthreads();
    }
    if (t == 0) out[OFF_LOSS] = red[0] / 64.f;
}

// ------------------------- launch -------------------------
extern "C" void kernel_launch(void* const* d_in, const int* in_sizes, int n_in,
                              void* d_out, int out_size) {
    const float* x        = (const float*)d_in[0];
    const float* context  = (const float*)d_in[1];
    const float* W_ih     = (const float*)d_in[2];
    const float* W_hh     = (const float*)d_in[3];
    const float* b_ih     = (const float*)d_in[4];
    const float* b_hh     = (const float*)d_in[5];
    const float* fw1      = (const float*)d_in[6];
    const float* fb1      = (const float*)d_in[7];
    const float* fw2      = (const float*)d_in[8];
    const float* fb2      = (const float*)d_in[9];
    const float* gw1      = (const float*)d_in[10];
    const float* gb1      = (const float*)d_in[11];
    const float* gw2      = (const float*)d_in[12];
    const float* gb2      = (const float*)d_in[13];
    const float* espec    = (const float*)d_in[14];
    float* out = (float*)d_out;

    float *XS, *GATES, *Hs, *Cs, *FH, *FLOW, *COMB, *G1, *ADJ;
    cudaGetSymbolAddress((void**)&XS,    d_XS);
    cudaGetSymbolAddress((void**)&GATES, d_GATES);
    cudaGetSymbolAddress((void**)&Hs,    d_Hst);
    cudaGetSymbolAddress((void**)&Cs,    d_Cst);
    cudaGetSymbolAddress((void**)&FH,    d_FH);
    cudaGetSymbolAddress((void**)&FLOW,  d_FLOW);
    cudaGetSymbolAddress((void**)&COMB,  d_COMB);
    cudaGetSymbolAddress((void**)&G1,    d_G1);
    cudaGetSymbolAddress((void**)&ADJ,   d_ADJ);

    // smem: 2 stages * (A hi/lo + B hi/lo), 144B row pitch, fp32 tiles
    const int SMEM128 = 2 * (2 * 128 * 144 + 2 * 128 * 144);  // 147456
    const int SMEM64  = 2 * (2 * 128 * 144 + 2 * 64 * 144);   // 110592
    cudaFuncSetAttribute(gemm_mma<128>, cudaFuncAttributeMaxDynamicSharedMemorySize, SMEM128);
    cudaFuncSetAttribute(gemm_mma<64>,  cudaFuncAttributeMaxDynamicSharedMemorySize, SMEM64);

    // 1: zero c state
    zero_kernel<<<(unsigned)(((size_t)BATCH * HH + 255) / 256), 256>>>(Cs, (size_t)BATCH * HH);

    // 2: XS = context @ W_ih^T + b_ih + b_hh (dual-bias epilogue)
    gemm_mma<128><<<dim3(G4H / 128, (BATCH * TT) / 128), 512, SMEM128>>>(
        context, DD, W_ih, DD, XS, G4H, DD, b_ih, b_hh, nullptr, 0, 0);

    // 3: flow hidden: relu(x @ fw1^T + fb1)  (independent of LSTM; moved early)
    gemm_mma<128><<<dim3(HH / 128, BATCH / 128), 512, SMEM128>>>(
        x, DD, fw1, DD, FH, HH, DD, fb1, nullptr, nullptr, 0, 1);

    // 4: flow_state softmax head
    flow2_kernel<<<BATCH / 8, 256>>>(FH, fw2, fb2, FLOW, out);

    // 5: t = 0 pointwise (h0 = 0)
    lstm_pw<<<(BATCH * HH + 255) / 256, 256>>>(XS, TT * G4H, Hs, Cs);

    // 6..17: recurrent steps — launch #6 (skip 5) is a GEMM => profiled by ncu
    for (int t = 1; t < TT; t++) {
        gemm_mma<128><<<dim3(G4H / 128, BATCH / 128), 512, SMEM128>>>(
            Hs, HH, W_hh, HH, GATES, G4H, HH, nullptr, nullptr, XS + (size_t)t * G4H, TT * G4H, 0);
        lstm_pw<<<(BATCH * HH + 255) / 256, 256>>>(GATES, G4H, Hs, Cs);
    }

    build_comb<<<(unsigned)(((size_t)BATCH * KCOMB + 255) / 256), 256>>>(x, Hs, FLOW, COMB);

    // gate hidden: relu(combined @ gw1^T + gb1), K = 1540 (ragged last chunk)
    gemm_mma<128><<<dim3(DD / 128, BATCH / 128), 512, SMEM128>>>(
        COMB, KCOMB, gw1, KCOMB, G1, DD, KCOMB, gb1, nullptr, nullptr, 0, 1);

    // gate logits: G1 @ gw2^T + gb2
    gemm_mma<64><<<dim3(EE / 64, BATCH / 128), 256, SMEM64>>>(
        G1, DD, gw2, DD, ADJ, EE, DD, gb2, nullptr, nullptr, 0, 0);

    zero_kernel<<<1, 64>>>(out + OFF_USAGE, EE);
    final_gate_kernel<<<BATCH / 8, 256>>>(ADJ, FLOW, espec, out);
    loss_kernel<<<1, 64>>>(out);
}

// round 13
// speedup vs baseline: 1.6785x; 1.1693x over previous
#include <cuda_runtime.h>
#include <cuda_fp16.h>
#include <cstdint>
#include <math.h>

#define BATCH 16384
#define TT 7
#define DD 1024
#define HH 512
#define EE 64
#define NF 4
#define G4H 2048              // 4*H
#define KCOMB 1540            // D + H + 4

// Output offsets (float32 concat in reference return order)
#define OFF_TOPP  ((size_t)0)
#define OFF_TOPI  ((size_t)131072)
#define OFF_LOSS  ((size_t)262144)
#define OFF_FLOW  ((size_t)262145)
#define OFF_USAGE ((size_t)327681)
#define OFF_ADJ   ((size_t)327745)

// ------------------------- scratch (static, no allocs) -------------------------
__device__ float d_XS[(size_t)BATCH * TT * G4H];
__device__ float d_GATES[(size_t)BATCH * G4H];
__device__ float d_Hst[(size_t)BATCH * HH];
__device__ float d_Cst[(size_t)BATCH * HH];
__device__ float d_FH[(size_t)BATCH * HH];
__device__ float d_FLOW[(size_t)BATCH * NF];
__device__ float d_COMB[(size_t)BATCH * KCOMB];
__device__ float d_G1[(size_t)BATCH * DD];
__device__ float d_ADJ[(size_t)BATCH * EE];

// ------------------------- helpers -------------------------
__device__ __forceinline__ uint32_t smem_u32(const void* p) {
    uint32_t a;
    asm("{ .reg .u64 t; cvta.to.shared.u64 t, %1; cvt.u32.u64 %0, t; }" : "=r"(a) : "l"(p));
    return a;
}
__device__ __forceinline__ void ldsm_x4(uint32_t* r, uint32_t addr) {
    asm volatile("ldmatrix.sync.aligned.m8n8.x4.shared.b16 {%0,%1,%2,%3}, [%4];"
        : "=r"(r[0]), "=r"(r[1]), "=r"(r[2]), "=r"(r[3]) : "r"(addr));
}
__device__ __forceinline__ void ldsm_x2(uint32_t* r, uint32_t addr) {
    asm volatile("ldmatrix.sync.aligned.m8n8.x2.shared.b16 {%0,%1}, [%2];"
        : "=r"(r[0]), "=r"(r[1]) : "r"(addr));
}
// tf32 mma: A 4 regs (m16k8), B 2 regs (k8n8), C 4 f32
__device__ __forceinline__ void mma1688(float* c, const uint32_t* a,
                                        uint32_t b0, uint32_t b1) {
    asm volatile(
        "mma.sync.aligned.m16n8k8.row.col.f32.tf32.tf32.f32 "
        "{%0,%1,%2,%3}, {%4,%5,%6,%7}, {%8,%9}, {%0,%1,%2,%3};"
        : "+f"(c[0]), "+f"(c[1]), "+f"(c[2]), "+f"(c[3])
        : "r"(a[0]), "r"(a[1]), "r"(a[2]), "r"(a[3]), "r"(b0), "r"(b1));
}
// fp16 mma k16 (fp32 accum) — used ONLY for correction terms
__device__ __forceinline__ void mma16816(float* c, const uint32_t* a, const uint32_t* b) {
    asm volatile(
        "mma.sync.aligned.m16n8k16.row.col.f32.f16.f16.f32 "
        "{%0,%1,%2,%3}, {%4,%5,%6,%7}, {%8,%9}, {%0,%1,%2,%3};"
        : "+f"(c[0]), "+f"(c[1]), "+f"(c[2]), "+f"(c[3])
        : "r"(a[0]), "r"(a[1]), "r"(a[2]), "r"(a[3]), "r"(b[0]), "r"(b[1]));
}
__device__ __forceinline__ float tf32_rnd(float v) {
    float r; asm("cvt.rna.tf32.f32 %0, %1;" : "=f"(r) : "f"(v)); return r;
}
__device__ __forceinline__ uint32_t pack2(__half a, __half b) {
    __half2 h = __halves2half2(a, b);
    return *reinterpret_cast<uint32_t*>(&h);
}
// split fp32 -> tf32 hi + tf32 lo
__device__ __forceinline__ void tsplit(float v, float& h, float& l) {
    h = tf32_rnd(v);
    l = tf32_rnd(v - h);
}

// ------------------------- mixed tf32/fp16 GEMM --------------------------------
// C[m,n] = sum_k A[m,k]*W[n,k] (+bias)(+bias2)(+addend)(relu)
// hh term: tf32 k8 MMAs (bit-identical to the frozen passing scheme).
// hl + lh correction terms: scaled fp16 k16 MMAs into a separate fp32 accum.
// BM=128, BK=32 fp32-k per chunk; BN in {128, 64}. Warp tile 32x32.
template<int BN>
__global__ void __launch_bounds__(128 * (BN / 32), 1)
gemm_mma(const float* __restrict__ A, int lda,
         const float* __restrict__ W, int ldw,
         float* __restrict__ C, int ldc, int K,
         const float* __restrict__ bias,
         const float* __restrict__ bias2,
         const float* __restrict__ addend, int add_ld,
         int relu)
{
    constexpr int BM = 128, BK = 32;
    constexpr int NW = 4 * (BN / 32);
    constexpr int T = 32 * NW;
    constexpr int P32 = 144;                 // tf32 tile pitch (bytes)
    constexpr int P16 = 80;                  // fp16 tile pitch (bytes)
    constexpr int A32SZ = BM * P32;
    constexpr int B32SZ = BN * P32;
    constexpr int A16SZ = BM * P16;
    constexpr int B16SZ = BN * P16;
    // stage layout: [aHi32][bHi32][aH16][aL16][bH16][bL16]
    constexpr int OFF_B32  = A32SZ;
    constexpr int OFF_A16H = OFF_B32 + B32SZ;
    constexpr int OFF_A16L = OFF_A16H + A16SZ;
    constexpr int OFF_B16H = OFF_A16L + A16SZ;
    constexpr int OFF_B16L = OFF_B16H + B16SZ;
    constexpr int STAGE = OFF_B16L + B16SZ;
    constexpr int AV = BM * BK / 4 / T;
    constexpr int BV = BN * BK / 4 / T;

    extern __shared__ char smem[];
    const uint32_t dsm = smem_u32(smem);

    const int tid = threadIdx.x;
    const int lane = tid & 31;
    const int wid = tid >> 5;
    const int wm = (wid & 3) * 32;
    const int wn = (wid >> 2) * 32;
    const long m0 = (long)blockIdx.y * BM;
    const int  n0 = blockIdx.x * BN;

    float Chh[2][4][4], Ccr[2][4][4];
#pragma unroll
    for (int i = 0; i < 2; i++)
#pragma unroll
        for (int j = 0; j < 4; j++)
#pragma unroll
            for (int q = 0; q < 4; q++) { Chh[i][j][q] = 0.f; Ccr[i][j][q] = 0.f; }

    float4 ra[AV], rb[BV];

    auto load_chunk = [&](int ch) {
        const int k0 = ch * BK;
#pragma unroll
        for (int q = 0; q < AV; q++) {
            int idx = tid + q * T;
            int row = idx >> 3, c4 = (idx & 7) * 4;
            ra[q] = (k0 + c4 < K)
                ? *reinterpret_cast<const float4*>(A + (m0 + row) * (long)lda + k0 + c4)
                : make_float4(0.f, 0.f, 0.f, 0.f);
        }
#pragma unroll
        for (int q = 0; q < BV; q++) {
            int idx = tid + q * T;
            int row = idx >> 3, c4 = (idx & 7) * 4;
            rb[q] = (k0 + c4 < K)
                ? *reinterpret_cast<const float4*>(W + (long)(n0 + row) * ldw + k0 + c4)
                : make_float4(0.f, 0.f, 0.f, 0.f);
        }
    };

    auto store_chunk = [&](int s) {
        char* st = smem + s * STAGE;
#pragma unroll
        for (int q = 0; q < AV; q++) {
            int idx = tid + q * T;
            int row = idx >> 3, c4 = (idx & 7) * 4;
            float4 h, l;
            tsplit(ra[q].x, h.x, l.x); tsplit(ra[q].y, h.y, l.y);
            tsplit(ra[q].z, h.z, l.z); tsplit(ra[q].w, h.w, l.w);
            *reinterpret_cast<float4*>(st + row * P32 + c4 * 4) = h;
            int o16 = row * P16 + c4 * 2;
            *reinterpret_cast<uint2*>(st + OFF_A16H + o16) = make_uint2(
                pack2(__float2half_rn(h.x), __float2half_rn(h.y)),
                pack2(__float2half_rn(h.z), __float2half_rn(h.w)));
            *reinterpret_cast<uint2*>(st + OFF_A16L + o16) = make_uint2(
                pack2(__float2half_rn(l.x * 2048.f), __float2half_rn(l.y * 2048.f)),
                pack2(__float2half_rn(l.z * 2048.f), __float2half_rn(l.w * 2048.f)));
        }
#pragma unroll
        for (int q = 0; q < BV; q++) {
            int idx = tid + q * T;
            int row = idx >> 3, c4 = (idx & 7) * 4;
            float4 h, l;
            tsplit(rb[q].x, h.x, l.x); tsplit(rb[q].y, h.y, l.y);
            tsplit(rb[q].z, h.z, l.z); tsplit(rb[q].w, h.w, l.w);
            *reinterpret_cast<float4*>(st + OFF_B32 + row * P32 + c4 * 4) = h;
            int o16 = row * P16 + c4 * 2;
            *reinterpret_cast<uint2*>(st + OFF_B16H + o16) = make_uint2(
                pack2(__float2half_rn(h.x), __float2half_rn(h.y)),
                pack2(__float2half_rn(h.z), __float2half_rn(h.w)));
            *reinterpret_cast<uint2*>(st + OFF_B16L + o16) = make_uint2(
                pack2(__float2half_rn(l.x * 2048.f), __float2half_rn(l.y * 2048.f)),
                pack2(__float2half_rn(l.z * 2048.f), __float2half_rn(l.w * 2048.f)));
        }
    };

    // tf32 ldmatrix per-lane offsets (R6/R12-verified)
    const uint32_t a32_off = (uint32_t)((lane & 15) * P32 + (lane >> 4) * 16);
    const uint32_t b32_off = (uint32_t)((((lane >> 3) & 1) * 8 + (lane & 7)) * P32
                                        + (lane >> 4) * 16);
    // fp16 ldmatrix per-lane offsets (R4-verified)
    const int ll = lane & 15;
    const uint32_t a16_off = (uint32_t)((wm + (lane & 15)) * P16 + (lane >> 4) * 16);
    const uint32_t b16_off = (uint32_t)((wn + (ll & 7)) * P16 + (ll >> 3) * 16);

    auto compute = [&](int s) {
        const uint32_t base = dsm + s * STAGE;
        // ---- tf32 hh (frozen numerics) ----
        const uint32_t aH = base + (uint32_t)(wm * P32) + a32_off;
        const uint32_t bH = base + OFF_B32 + (uint32_t)(wn * P32) + b32_off;
#pragma unroll
        for (int ks = 0; ks < 4; ks++) {
            uint32_t ah[2][4];
            uint32_t bh[4][2];
#pragma unroll
            for (int mi = 0; mi < 2; mi++)
                ldsm_x4(ah[mi], aH + mi * 16 * P32 + ks * 32);
#pragma unroll
            for (int p = 0; p < 2; p++) {
                uint32_t t[4];
                ldsm_x4(t, bH + p * 16 * P32 + ks * 32);
                bh[2*p][0] = t[0]; bh[2*p][1] = t[2];
                bh[2*p+1][0] = t[1]; bh[2*p+1][1] = t[3];
            }
#pragma unroll
            for (int mi = 0; mi < 2; mi++)
#pragma unroll
                for (int ni = 0; ni < 4; ni++)
                    mma1688(Chh[mi][ni], ah[mi], bh[ni][0], bh[ni][1]);
        }
        // ---- fp16 corrections: aH*bL + aL*bH (scaled 2^11) ----
        const uint32_t aHh = base + OFF_A16H + a16_off;
        const uint32_t aLh = base + OFF_A16L + a16_off;
        const uint32_t bHh = base + OFF_B16H + b16_off;
        const uint32_t bLh = base + OFF_B16L + b16_off;
#pragma unroll
        for (int ks = 0; ks < 2; ks++) {
            uint32_t ah16[2][4], al16[2][4], bh16[4][2], bl16[4][2];
#pragma unroll
            for (int mi = 0; mi < 2; mi++) {
                ldsm_x4(ah16[mi], aHh + mi * 16 * P16 + ks * 32);
                ldsm_x4(al16[mi], aLh + mi * 16 * P16 + ks * 32);
            }
#pragma unroll
            for (int ni = 0; ni < 4; ni++) {
                ldsm_x2(bh16[ni], bHh + ni * 8 * P16 + ks * 32);
                ldsm_x2(bl16[ni], bLh + ni * 8 * P16 + ks * 32);
            }
#pragma unroll
            for (int mi = 0; mi < 2; mi++)
#pragma unroll
                for (int ni = 0; ni < 4; ni++)
                    mma16816(Ccr[mi][ni], ah16[mi], bl16[ni]);
#pragma unroll
            for (int mi = 0; mi < 2; mi++)
#pragma unroll
                for (int ni = 0; ni < 4; ni++)
                    mma16816(Ccr[mi][ni], al16[mi], bh16[ni]);
        }
    };

    const int nch = (K + BK - 1) / BK;

    load_chunk(0);
    store_chunk(0);
    __syncthreads();

    for (int i = 0; i < nch; i++) {
        const int s = i & 1;
        if (i + 1 < nch) load_chunk(i + 1);
        compute(s);
        if (i + 1 < nch) {
            store_chunk(s ^ 1);
            __syncthreads();
        }
    }

    // epilogue: C = Chh + Ccr/2048 (+bias)(+bias2)(+addend)(relu)
    const float sc = 1.0f / 2048.0f;
#pragma unroll
    for (int mi = 0; mi < 2; mi++)
#pragma unroll
        for (int ni = 0; ni < 4; ni++)
#pragma unroll
            for (int h = 0; h < 2; h++) {
                long row = m0 + wm + mi * 16 + (lane >> 2) + h * 8;
                int  col = n0 + wn + ni * 8 + (lane & 3) * 2;
                float v0 = Chh[mi][ni][2 * h + 0] + sc * Ccr[mi][ni][2 * h + 0];
                float v1 = Chh[mi][ni][2 * h + 1] + sc * Ccr[mi][ni][2 * h + 1];
                if (bias)  { v0 += bias[col];  v1 += bias[col + 1]; }
                if (bias2) { v0 += bias2[col]; v1 += bias2[col + 1]; }
                if (addend) {
                    float2 ad = *reinterpret_cast<const float2*>(addend + row * (long)add_ld + col);
                    v0 += ad.x; v1 += ad.y;
                }
                if (relu) { v0 = fmaxf(v0, 0.f); v1 = fmaxf(v1, 0.f); }
                *reinterpret_cast<float2*>(C + row * (long)ldc + col) = make_float2(v0, v1);
            }
}

// ------------------------- small kernels -------------------------
__global__ void zero_kernel(float* __restrict__ p, size_t n) {
    size_t i = (size_t)blockIdx.x * blockDim.x + threadIdx.x;
    if (i < n) p[i] = 0.f;
}

__device__ __forceinline__ float sigmoidf(float x) { return 1.f / (1.f + expf(-x)); }

__global__ void lstm_pw(const float* __restrict__ gates, int rstride,
                        float* __restrict__ Hs, float* __restrict__ Cs) {
    int idx = blockIdx.x * blockDim.x + threadIdx.x;
    if (idx >= BATCH * HH) return;
    int b = idx / HH, j = idx % HH;
    const float* g = gates + (size_t)b * rstride;
    float gi = g[j], gf = g[HH + j], gg = g[2 * HH + j], go = g[3 * HH + j];
    float c = sigmoidf(gf) * Cs[idx] + sigmoidf(gi) * tanhf(gg);
    Cs[idx] = c;
    Hs[idx] = sigmoidf(go) * tanhf(c);
}

__global__ void flow2_kernel(const float* __restrict__ FHp,
                             const float* __restrict__ fw2,
                             const float* __restrict__ fb2,
                             float* __restrict__ FLOWp,
                             float* __restrict__ out) {
    __shared__ float w[NF * HH];
    int tid = threadIdx.x;
    for (int q = tid; q < NF * HH; q += blockDim.x) w[q] = fw2[q];
    __syncthreads();
    int warp = tid >> 5, lane = tid & 31;
    int b = blockIdx.x * 8 + warp;
    const float* r = FHp + (size_t)b * HH;
    float a0 = 0.f, a1 = 0.f, a2 = 0.f, a3 = 0.f;
    for (int k = lane; k < HH; k += 32) {
        float v = r[k];
        a0 += v * w[k];
        a1 += v * w[HH + k];
        a2 += v * w[2 * HH + k];
        a3 += v * w[3 * HH + k];
    }
#pragma unroll
    for (int off = 16; off; off >>= 1) {
        a0 += __shfl_xor_sync(0xffffffffu, a0, off);
        a1 += __shfl_xor_sync(0xffffffffu, a1, off);
        a2 += __shfl_xor_sync(0xffffffffu, a2, off);
        a3 += __shfl_xor_sync(0xffffffffu, a3, off);
    }
    if (lane == 0) {
        a0 += fb2[0]; a1 += fb2[1]; a2 += fb2[2]; a3 += fb2[3];
        float m = fmaxf(fmaxf(a0, a1), fmaxf(a2, a3));
        float e0 = expf(a0 - m), e1 = expf(a1 - m), e2 = expf(a2 - m), e3 = expf(a3 - m);
        float inv = 1.f / (e0 + e1 + e2 + e3);
        float p0 = e0 * inv, p1 = e1 * inv, p2 = e2 * inv, p3 = e3 * inv;
        FLOWp[b * 4 + 0] = p0; FLOWp[b * 4 + 1] = p1;
        FLOWp[b * 4 + 2] = p2; FLOWp[b * 4 + 3] = p3;
        out[OFF_FLOW + b * 4 + 0] = p0; out[OFF_FLOW + b * 4 + 1] = p1;
        out[OFF_FLOW + b * 4 + 2] = p2; out[OFF_FLOW + b * 4 + 3] = p3;
    }
}

__global__ void build_comb(const float* __restrict__ x,
                           const float* __restrict__ Hs,
                           const float* __restrict__ FLOWp,
                           float* __restrict__ comb) {
    size_t idx = (size_t)blockIdx.x * blockDim.x + threadIdx.x;
    if (idx >= (size_t)BATCH * KCOMB) return;
    int b = (int)(idx / KCOMB), c = (int)(idx % KCOMB);
    float v;
    if (c < DD)            v = x[(size_t)b * DD + c];
    else if (c < DD + HH)  v = Hs[(size_t)b * HH + (c - DD)];
    else                   v = FLOWp[b * 4 + (c - DD - HH)];
    comb[idx] = v;
}

__global__ void final_gate_kernel(const float* __restrict__ adjraw,
                                  const float* __restrict__ flow,
                                  const float* __restrict__ spec,
                                  float* __restrict__ out) {
    __shared__ float s_spec[EE * NF];
    __shared__ float s_usage[EE];
    int tid = threadIdx.x;
    if (tid < EE * NF) s_spec[tid] = spec[tid];
    if (tid < EE)      s_usage[tid] = 0.f;
    __syncthreads();

    int warp = tid >> 5, lane = tid & 31;
    int b = blockIdx.x * 8 + warp;

    float f0 = flow[b * 4 + 0], f1 = flow[b * 4 + 1], f2 = flow[b * 4 + 2], f3 = flow[b * 4 + 3];
    int e0 = lane, e1 = lane + 32;
    float sp0 = 0.1f * (f0 * s_spec[e0 * 4 + 0] + f1 * s_spec[e0 * 4 + 1] +
                        f2 * s_spec[e0 * 4 + 2] + f3 * s_spec[e0 * 4 + 3]);
    float sp1 = 0.1f * (f0 * s_spec[e1 * 4 + 0] + f1 * s_spec[e1 * 4 + 1] +
                        f2 * s_spec[e1 * 4 + 2] + f3 * s_spec[e1 * 4 + 3]);
    float l0 = adjraw[(size_t)b * EE + e0] + sp0;
    float l1 = adjraw[(size_t)b * EE + e1] + sp1;
    out[OFF_ADJ + (size_t)b * EE + e0] = l0;
    out[OFF_ADJ + (size_t)b * EE + e1] = l1;

    float m = fmaxf(l0, l1);
#pragma unroll
    for (int off = 16; off; off >>= 1) m = fmaxf(m, __shfl_xor_sync(0xffffffffu, m, off));
    float x0 = expf(l0 - m), x1 = expf(l1 - m);
    float s = x0 + x1;
#pragma unroll
    for (int off = 16; off; off >>= 1) s += __shfl_xor_sync(0xffffffffu, s, off);
    float inv_s = 1.f / s;
    float p0 = x0 * inv_s, p1 = x1 * inv_s;

    atomicAdd(&s_usage[e0], p0);
    atomicAdd(&s_usage[e1], p1);

    float tp[8]; int ti[8];
    float v0 = p0, v1 = p1;
#pragma unroll
    for (int it = 0; it < 8; it++) {
        float v; int bi;
        if (v1 > v0) { v = v1; bi = e1; } else { v = v0; bi = e0; }
#pragma unroll
        for (int off = 16; off; off >>= 1) {
            float ov = __shfl_xor_sync(0xffffffffu, v, off);
            int   oi = __shfl_xor_sync(0xffffffffu, bi, off);
            if (ov > v || (ov == v && oi < bi)) { v = ov; bi = oi; }
        }
        tp[it] = v; ti[it] = bi;
        if (bi == e0) v0 = -1.f;
        if (bi == e1) v1 = -1.f;
    }
    float ssum = 0.f;
#pragma unroll
    for (int it = 0; it < 8; it++) ssum += tp[it];
    float invn = 1.f / (ssum + 1e-8f);
    if (lane < 8) {
        out[OFF_TOPP + (size_t)b * 8 + lane] = tp[lane] * invn;
        out[OFF_TOPI + (size_t)b * 8 + lane] = (float)ti[lane];
    }
    __syncthreads();
    if (tid < EE) atomicAdd(&out[OFF_USAGE + tid], s_usage[tid]);
}

__global__ void loss_kernel(float* __restrict__ out) {
    __shared__ float red[EE];
    int t = threadIdx.x;  // 64 threads
    float u = out[OFF_USAGE + t] / (float)BATCH;
    out[OFF_USAGE + t] = u;
    red[t] = -(1.0f / 64.f) * log1pf(64.f * u - 1.f);
    __syncthreads();
    for (int s = 32; s; s >>= 1) {
        if (t < s) red[t] += red[t + s];
        __syncthreads();
    }
    if (t == 0) out[OFF_LOSS] = red[0] / 64.f;
}

// ------------------------- launch -------------------------
extern "C" void kernel_launch(void* const* d_in, const int* in_sizes, int n_in,
                              void* d_out, int out_size) {
    const float* x        = (const float*)d_in[0];
    const float* context  = (const float*)d_in[1];
    const float* W_ih     = (const float*)d_in[2];
    const float* W_hh     = (const float*)d_in[3];
    const float* b_ih     = (const float*)d_in[4];
    const float* b_hh     = (const float*)d_in[5];
    const float* fw1      = (const float*)d_in[6];
    const float* fb1      = (const float*)d_in[7];
    const float* fw2      = (const float*)d_in[8];
    const float* fb2      = (const float*)d_in[9];
    const float* gw1      = (const float*)d_in[10];
    const float* gb1      = (const float*)d_in[11];
    const float* gw2      = (const float*)d_in[12];
    const float* gb2      = (const float*)d_in[13];
    const float* espec    = (const float*)d_in[14];
    float* out = (float*)d_out;

    float *XS, *GATES, *Hs, *Cs, *FH, *FLOW, *COMB, *G1, *ADJ;
    cudaGetSymbolAddress((void**)&XS,    d_XS);
    cudaGetSymbolAddress((void**)&GATES, d_GATES);
    cudaGetSymbolAddress((void**)&Hs,    d_Hst);
    cudaGetSymbolAddress((void**)&Cs,    d_Cst);
    cudaGetSymbolAddress((void**)&FH,    d_FH);
    cudaGetSymbolAddress((void**)&FLOW,  d_FLOW);
    cudaGetSymbolAddress((void**)&COMB,  d_COMB);
    cudaGetSymbolAddress((void**)&G1,    d_G1);
    cudaGetSymbolAddress((void**)&ADJ,   d_ADJ);

    // smem: 2 stages * ([A,B] tf32-hi + [A,B] fp16 hi/lo)
    const int SMEM128 = 2 * ((128 + 128) * 144 + 2 * (128 + 128) * 80);  // 155648
    const int SMEM64  = 2 * ((128 + 64) * 144 + 2 * (128 + 64) * 80);    // 116736
    cudaFuncSetAttribute(gemm_mma<128>, cudaFuncAttributeMaxDynamicSharedMemorySize, SMEM128);
    cudaFuncSetAttribute(gemm_mma<64>,  cudaFuncAttributeMaxDynamicSharedMemorySize, SMEM64);

    // 1: zero c state
    zero_kernel<<<(unsigned)(((size_t)BATCH * HH + 255) / 256), 256>>>(Cs, (size_t)BATCH * HH);

    // 2: XS = context @ W_ih^T + b_ih + b_hh
    gemm_mma<128><<<dim3(G4H / 128, (BATCH * TT) / 128), 512, SMEM128>>>(
        context, DD, W_ih, DD, XS, G4H, DD, b_ih, b_hh, nullptr, 0, 0);

    // 3: flow hidden: relu(x @ fw1^T + fb1)
    gemm_mma<128><<<dim3(HH / 128, BATCH / 128), 512, SMEM128>>>(
        x, DD, fw1, DD, FH, HH, DD, fb1, nullptr, nullptr, 0, 1);

    // 4: flow_state softmax head
    flow2_kernel<<<BATCH / 8, 256>>>(FH, fw2, fb2, FLOW, out);

    // 5: t = 0 pointwise (h0 = 0)
    lstm_pw<<<(BATCH * HH + 255) / 256, 256>>>(XS, TT * G4H, Hs, Cs);

    // 6..: recurrent steps
    for (int t = 1; t < TT; t++) {
        gemm_mma<128><<<dim3(G4H / 128, BATCH / 128), 512, SMEM128>>>(
            Hs, HH, W_hh, HH, GATES, G4H, HH, nullptr, nullptr, XS + (size_t)t * G4H, TT * G4H, 0);
        lstm_pw<<<(BATCH * HH + 255) / 256, 256>>>(GATES, G4H, Hs, Cs);
    }

    build_comb<<<(unsigned)(((size_t)BATCH * KCOMB + 255) / 256), 256>>>(x, Hs, FLOW, COMB);

    // gate hidden: relu(combined @ gw1^T + gb1), K = 1540 (ragged last chunk)
    gemm_mma<128><<<dim3(DD / 128, BATCH / 128), 512, SMEM128>>>(
        COMB, KCOMB, gw1, KCOMB, G1, DD, KCOMB, gb1, nullptr, nullptr, 0, 1);

    // gate logits: G1 @ gw2^T + gb2
    gemm_mma<64><<<dim3(EE / 64, BATCH / 128), 256, SMEM64>>>(
        G1, DD, gw2, DD, ADJ, EE, DD, gb2, nullptr, nullptr, 0, 0);

    zero_kernel<<<1, 64>>>(out + OFF_USAGE, EE);
    final_gate_kernel<<<BATCH / 8, 256>>>(ADJ, FLOW, espec, out);
    loss_kernel<<<1, 64>>>(out);
}

// round 14
// speedup vs baseline: 1.7086x; 1.0179x over previous
#include <cuda_runtime.h>
#include <cuda_fp16.h>
#include <cstdint>
#include <math.h>

#define BATCH 16384
#define TT 7
#define DD 1024
#define HH 512
#define EE 64
#define NF 4
#define G4H 2048              // 4*H
#define KCOMB 1540            // D + H + 4

// Output offsets (float32 concat in reference return order)
#define OFF_TOPP  ((size_t)0)
#define OFF_TOPI  ((size_t)131072)
#define OFF_LOSS  ((size_t)262144)
#define OFF_FLOW  ((size_t)262145)
#define OFF_USAGE ((size_t)327681)
#define OFF_ADJ   ((size_t)327745)

// ------------------------- scratch (static, no allocs) -------------------------
__device__ float d_XS[(size_t)BATCH * TT * G4H];
__device__ float d_Hst[(size_t)BATCH * HH];
__device__ float d_Hst2[(size_t)BATCH * HH];
__device__ float d_Cst[(size_t)BATCH * HH];
__device__ float d_FH[(size_t)BATCH * HH];
__device__ float d_FLOW[(size_t)BATCH * NF];
__device__ float d_COMB[(size_t)BATCH * KCOMB];
__device__ float d_G1[(size_t)BATCH * DD];
__device__ float d_ADJ[(size_t)BATCH * EE];
__device__ float d_WIH2[(size_t)G4H * DD];
__device__ float d_WHH2[(size_t)G4H * HH];
__device__ float d_BSUM2[G4H];

// ------------------------- helpers -------------------------
__device__ __forceinline__ uint32_t smem_u32(const void* p) {
    uint32_t a;
    asm("{ .reg .u64 t; cvta.to.shared.u64 t, %1; cvt.u32.u64 %0, t; }" : "=r"(a) : "l"(p));
    return a;
}
__device__ __forceinline__ void ldsm_x4(uint32_t* r, uint32_t addr) {
    asm volatile("ldmatrix.sync.aligned.m8n8.x4.shared.b16 {%0,%1,%2,%3}, [%4];"
        : "=r"(r[0]), "=r"(r[1]), "=r"(r[2]), "=r"(r[3]) : "r"(addr));
}
__device__ __forceinline__ void ldsm_x2(uint32_t* r, uint32_t addr) {
    asm volatile("ldmatrix.sync.aligned.m8n8.x2.shared.b16 {%0,%1}, [%2];"
        : "=r"(r[0]), "=r"(r[1]) : "r"(addr));
}
__device__ __forceinline__ void mma1688(float* c, const uint32_t* a,
                                        uint32_t b0, uint32_t b1) {
    asm volatile(
        "mma.sync.aligned.m16n8k8.row.col.f32.tf32.tf32.f32 "
        "{%0,%1,%2,%3}, {%4,%5,%6,%7}, {%8,%9}, {%0,%1,%2,%3};"
        : "+f"(c[0]), "+f"(c[1]), "+f"(c[2]), "+f"(c[3])
        : "r"(a[0]), "r"(a[1]), "r"(a[2]), "r"(a[3]), "r"(b0), "r"(b1));
}
__device__ __forceinline__ void mma16816(float* c, const uint32_t* a, const uint32_t* b) {
    asm volatile(
        "mma.sync.aligned.m16n8k16.row.col.f32.f16.f16.f32 "
        "{%0,%1,%2,%3}, {%4,%5,%6,%7}, {%8,%9}, {%0,%1,%2,%3};"
        : "+f"(c[0]), "+f"(c[1]), "+f"(c[2]), "+f"(c[3])
        : "r"(a[0]), "r"(a[1]), "r"(a[2]), "r"(a[3]), "r"(b[0]), "r"(b[1]));
}
__device__ __forceinline__ float tf32_rnd(float v) {
    float r; asm("cvt.rna.tf32.f32 %0, %1;" : "=f"(r) : "f"(v)); return r;
}
__device__ __forceinline__ uint32_t pack2(__half a, __half b) {
    __half2 h = __halves2half2(a, b);
    return *reinterpret_cast<uint32_t*>(&h);
}
__device__ __forceinline__ void tsplit(float v, float& h, float& l) {
    h = tf32_rnd(v);
    l = tf32_rnd(v - h);
}
__device__ __forceinline__ float sigmoidf(float x) { return 1.f / (1.f + expf(-x)); }

// ======================= shared GEMM machinery (macro-free via includes) =====
// Core: BM=128, BK=32 fp32-k; hh in tf32 k8 (frozen), hl+lh in scaled fp16 k16.

template<int BN>
struct GemmCore {
    static constexpr int BM = 128, BK = 32;
    static constexpr int NW = 4 * (BN / 32);
    static constexpr int T = 32 * NW;
    static constexpr int P32 = 144;
    static constexpr int P16 = 80;
    static constexpr int A32SZ = BM * P32;
    static constexpr int B32SZ = BN * P32;
    static constexpr int A16SZ = BM * P16;
    static constexpr int B16SZ = BN * P16;
    static constexpr int OFF_B32  = A32SZ;
    static constexpr int OFF_A16H = OFF_B32 + B32SZ;
    static constexpr int OFF_A16L = OFF_A16H + A16SZ;
    static constexpr int OFF_B16H = OFF_A16L + A16SZ;
    static constexpr int OFF_B16L = OFF_B16H + B16SZ;
    static constexpr int STAGE = OFF_B16L + B16SZ;
    static constexpr int AV = BM * BK / 4 / T;
    static constexpr int BV = BN * BK / 4 / T;
};

// ------------------------- generic GEMM (non-fused epilogue) -----------------
template<int BN>
__global__ void __launch_bounds__(128 * (BN / 32), 1)
gemm_mma(const float* __restrict__ A, int lda,
         const float* __restrict__ W, int ldw,
         float* __restrict__ C, int ldc, int K,
         const float* __restrict__ bias,
         const float* __restrict__ addend, int add_ld,
         int relu)
{
    using G = GemmCore<BN>;
    extern __shared__ char smem[];
    const uint32_t dsm = smem_u32(smem);

    const int tid = threadIdx.x;
    const int lane = tid & 31;
    const int wid = tid >> 5;
    const int wm = (wid & 3) * 32;
    const int wn = (wid >> 2) * 32;
    const long m0 = (long)blockIdx.y * G::BM;
    const int  n0 = blockIdx.x * BN;

    float Chh[2][4][4], Ccr[2][4][4];
#pragma unroll
    for (int i = 0; i < 2; i++)
#pragma unroll
        for (int j = 0; j < 4; j++)
#pragma unroll
            for (int q = 0; q < 4; q++) { Chh[i][j][q] = 0.f; Ccr[i][j][q] = 0.f; }

    float4 ra[G::AV], rb[G::BV];

    auto load_chunk = [&](int ch) {
        const int k0 = ch * G::BK;
#pragma unroll
        for (int q = 0; q < G::AV; q++) {
            int idx = tid + q * G::T;
            int row = idx >> 3, c4 = (idx & 7) * 4;
            ra[q] = (k0 + c4 < K)
                ? *reinterpret_cast<const float4*>(A + (m0 + row) * (long)lda + k0 + c4)
                : make_float4(0.f, 0.f, 0.f, 0.f);
        }
#pragma unroll
        for (int q = 0; q < G::BV; q++) {
            int idx = tid + q * G::T;
            int row = idx >> 3, c4 = (idx & 7) * 4;
            rb[q] = (k0 + c4 < K)
                ? *reinterpret_cast<const float4*>(W + (long)(n0 + row) * ldw + k0 + c4)
                : make_float4(0.f, 0.f, 0.f, 0.f);
        }
    };

    auto store_chunk = [&](int s) {
        char* st = smem + s * G::STAGE;
#pragma unroll
        for (int q = 0; q < G::AV; q++) {
            int idx = tid + q * G::T;
            int row = idx >> 3, c4 = (idx & 7) * 4;
            float4 h, l;
            tsplit(ra[q].x, h.x, l.x); tsplit(ra[q].y, h.y, l.y);
            tsplit(ra[q].z, h.z, l.z); tsplit(ra[q].w, h.w, l.w);
            *reinterpret_cast<float4*>(st + row * G::P32 + c4 * 4) = h;
            int o16 = row * G::P16 + c4 * 2;
            *reinterpret_cast<uint2*>(st + G::OFF_A16H + o16) = make_uint2(
                pack2(__float2half_rn(h.x), __float2half_rn(h.y)),
                pack2(__float2half_rn(h.z), __float2half_rn(h.w)));
            *reinterpret_cast<uint2*>(st + G::OFF_A16L + o16) = make_uint2(
                pack2(__float2half_rn(l.x * 2048.f), __float2half_rn(l.y * 2048.f)),
                pack2(__float2half_rn(l.z * 2048.f), __float2half_rn(l.w * 2048.f)));
        }
#pragma unroll
        for (int q = 0; q < G::BV; q++) {
            int idx = tid + q * G::T;
            int row = idx >> 3, c4 = (idx & 7) * 4;
            float4 h, l;
            tsplit(rb[q].x, h.x, l.x); tsplit(rb[q].y, h.y, l.y);
            tsplit(rb[q].z, h.z, l.z); tsplit(rb[q].w, h.w, l.w);
            *reinterpret_cast<float4*>(st + G::OFF_B32 + row * G::P32 + c4 * 4) = h;
            int o16 = row * G::P16 + c4 * 2;
            *reinterpret_cast<uint2*>(st + G::OFF_B16H + o16) = make_uint2(
                pack2(__float2half_rn(h.x), __float2half_rn(h.y)),
                pack2(__float2half_rn(h.z), __float2half_rn(h.w)));
            *reinterpret_cast<uint2*>(st + G::OFF_B16L + o16) = make_uint2(
                pack2(__float2half_rn(l.x * 2048.f), __float2half_rn(l.y * 2048.f)),
                pack2(__float2half_rn(l.z * 2048.f), __float2half_rn(l.w * 2048.f)));
        }
    };

    const uint32_t a32_off = (uint32_t)((lane & 15) * G::P32 + (lane >> 4) * 16);
    const uint32_t b32_off = (uint32_t)((((lane >> 3) & 1) * 8 + (lane & 7)) * G::P32
                                        + (lane >> 4) * 16);
    const int ll = lane & 15;
    const uint32_t a16_off = (uint32_t)((wm + (lane & 15)) * G::P16 + (lane >> 4) * 16);
    const uint32_t b16_off = (uint32_t)((wn + (ll & 7)) * G::P16 + (ll >> 3) * 16);

    auto compute = [&](int s) {
        const uint32_t base = dsm + s * G::STAGE;
        const uint32_t aH = base + (uint32_t)(wm * G::P32) + a32_off;
        const uint32_t bH = base + G::OFF_B32 + (uint32_t)(wn * G::P32) + b32_off;
#pragma unroll
        for (int ks = 0; ks < 4; ks++) {
            uint32_t ah[2][4];
            uint32_t bh[4][2];
#pragma unroll
            for (int mi = 0; mi < 2; mi++)
                ldsm_x4(ah[mi], aH + mi * 16 * G::P32 + ks * 32);
#pragma unroll
            for (int p = 0; p < 2; p++) {
                uint32_t t[4];
                ldsm_x4(t, bH + p * 16 * G::P32 + ks * 32);
                bh[2*p][0] = t[0]; bh[2*p][1] = t[2];
                bh[2*p+1][0] = t[1]; bh[2*p+1][1] = t[3];
            }
#pragma unroll
            for (int mi = 0; mi < 2; mi++)
#pragma unroll
                for (int ni = 0; ni < 4; ni++)
                    mma1688(Chh[mi][ni], ah[mi], bh[ni][0], bh[ni][1]);
        }
        const uint32_t aHh = base + G::OFF_A16H + a16_off;
        const uint32_t aLh = base + G::OFF_A16L + a16_off;
        const uint32_t bHh = base + G::OFF_B16H + b16_off;
        const uint32_t bLh = base + G::OFF_B16L + b16_off;
#pragma unroll
        for (int ks = 0; ks < 2; ks++) {
            uint32_t ah16[2][4], al16[2][4], bh16[4][2], bl16[4][2];
#pragma unroll
            for (int mi = 0; mi < 2; mi++) {
                ldsm_x4(ah16[mi], aHh + mi * 16 * G::P16 + ks * 32);
                ldsm_x4(al16[mi], aLh + mi * 16 * G::P16 + ks * 32);
            }
#pragma unroll
            for (int ni = 0; ni < 4; ni++) {
                ldsm_x2(bh16[ni], bHh + ni * 8 * G::P16 + ks * 32);
                ldsm_x2(bl16[ni], bLh + ni * 8 * G::P16 + ks * 32);
            }
#pragma unroll
            for (int mi = 0; mi < 2; mi++)
#pragma unroll
                for (int ni = 0; ni < 4; ni++)
                    mma16816(Ccr[mi][ni], ah16[mi], bl16[ni]);
#pragma unroll
            for (int mi = 0; mi < 2; mi++)
#pragma unroll
                for (int ni = 0; ni < 4; ni++)
                    mma16816(Ccr[mi][ni], al16[mi], bh16[ni]);
        }
    };

    const int nch = (K + G::BK - 1) / G::BK;
    load_chunk(0);
    store_chunk(0);
    __syncthreads();
    for (int i = 0; i < nch; i++) {
        const int s = i & 1;
        if (i + 1 < nch) load_chunk(i + 1);
        compute(s);
        if (i + 1 < nch) {
            store_chunk(s ^ 1);
            __syncthreads();
        }
    }

    const float sc = 1.0f / 2048.0f;
#pragma unroll
    for (int mi = 0; mi < 2; mi++)
#pragma unroll
        for (int ni = 0; ni < 4; ni++)
#pragma unroll
            for (int h = 0; h < 2; h++) {
                long row = m0 + wm + mi * 16 + (lane >> 2) + h * 8;
                int  col = n0 + wn + ni * 8 + (lane & 3) * 2;
                float v0 = Chh[mi][ni][2 * h + 0] + sc * Ccr[mi][ni][2 * h + 0];
                float v1 = Chh[mi][ni][2 * h + 1] + sc * Ccr[mi][ni][2 * h + 1];
                if (bias)  { v0 += bias[col];  v1 += bias[col + 1]; }
                if (addend) {
                    float2 ad = *reinterpret_cast<const float2*>(addend + row * (long)add_ld + col);
                    v0 += ad.x; v1 += ad.y;
                }
                if (relu) { v0 = fmaxf(v0, 0.f); v1 = fmaxf(v1, 0.f); }
                *reinterpret_cast<float2*>(C + row * (long)ldc + col) = make_float2(v0, v1);
            }
}

// ------------------------- fused recurrent GEMM + LSTM pointwise -------------
// gates = Hin @ WHH2^T + XS_t (interleaved cols: unit j gates at 4j..4j+3)
// Epilogue: c = sig(f)*c_old + sig(i)*tanh(g); h = sig(o)*tanh(c)
__global__ void __launch_bounds__(512, 1)
gemm_lstm(const float* __restrict__ Hin,
          const float* __restrict__ W,        // WHH2, ldw = HH
          const float* __restrict__ addend,   // XS + t*G4H, add_ld = TT*G4H
          float* __restrict__ Hout,
          float* __restrict__ Cs)
{
    using G = GemmCore<128>;
    constexpr int BN = 128;
    extern __shared__ char smem[];
    const uint32_t dsm = smem_u32(smem);

    const int tid = threadIdx.x;
    const int lane = tid & 31;
    const int wid = tid >> 5;
    const int wm = (wid & 3) * 32;
    const int wn = (wid >> 2) * 32;
    const long m0 = (long)blockIdx.y * G::BM;
    const int  n0 = blockIdx.x * BN;
    const int  K = HH;

    float Chh[2][4][4], Ccr[2][4][4];
#pragma unroll
    for (int i = 0; i < 2; i++)
#pragma unroll
        for (int j = 0; j < 4; j++)
#pragma unroll
            for (int q = 0; q < 4; q++) { Chh[i][j][q] = 0.f; Ccr[i][j][q] = 0.f; }

    float4 ra[G::AV], rb[G::BV];

    auto load_chunk = [&](int ch) {
        const int k0 = ch * G::BK;
#pragma unroll
        for (int q = 0; q < G::AV; q++) {
            int idx = tid + q * G::T;
            int row = idx >> 3, c4 = (idx & 7) * 4;
            ra[q] = *reinterpret_cast<const float4*>(Hin + (m0 + row) * (long)HH + k0 + c4);
        }
#pragma unroll
        for (int q = 0; q < G::BV; q++) {
            int idx = tid + q * G::T;
            int row = idx >> 3, c4 = (idx & 7) * 4;
            rb[q] = *reinterpret_cast<const float4*>(W + (long)(n0 + row) * HH + k0 + c4);
        }
    };

    auto store_chunk = [&](int s) {
        char* st = smem + s * G::STAGE;
#pragma unroll
        for (int q = 0; q < G::AV; q++) {
            int idx = tid + q * G::T;
            int row = idx >> 3, c4 = (idx & 7) * 4;
            float4 h, l;
            tsplit(ra[q].x, h.x, l.x); tsplit(ra[q].y, h.y, l.y);
            tsplit(ra[q].z, h.z, l.z); tsplit(ra[q].w, h.w, l.w);
            *reinterpret_cast<float4*>(st + row * G::P32 + c4 * 4) = h;
            int o16 = row * G::P16 + c4 * 2;
            *reinterpret_cast<uint2*>(st + G::OFF_A16H + o16) = make_uint2(
                pack2(__float2half_rn(h.x), __float2half_rn(h.y)),
                pack2(__float2half_rn(h.z), __float2half_rn(h.w)));
            *reinterpret_cast<uint2*>(st + G::OFF_A16L + o16) = make_uint2(
                pack2(__float2half_rn(l.x * 2048.f), __float2half_rn(l.y * 2048.f)),
                pack2(__float2half_rn(l.z * 2048.f), __float2half_rn(l.w * 2048.f)));
        }
#pragma unroll
        for (int q = 0; q < G::BV; q++) {
            int idx = tid + q * G::T;
            int row = idx >> 3, c4 = (idx & 7) * 4;
            float4 h, l;
            tsplit(rb[q].x, h.x, l.x); tsplit(rb[q].y, h.y, l.y);
            tsplit(rb[q].z, h.z, l.z); tsplit(rb[q].w, h.w, l.w);
            *reinterpret_cast<float4*>(st + G::OFF_B32 + row * G::P32 + c4 * 4) = h;
            int o16 = row * G::P16 + c4 * 2;
            *reinterpret_cast<uint2*>(st + G::OFF_B16H + o16) = make_uint2(
                pack2(__float2half_rn(h.x), __float2half_rn(h.y)),
                pack2(__float2half_rn(h.z), __float2half_rn(h.w)));
            *reinterpret_cast<uint2*>(st + G::OFF_B16L + o16) = make_uint2(
                pack2(__float2half_rn(l.x * 2048.f), __float2half_rn(l.y * 2048.f)),
                pack2(__float2half_rn(l.z * 2048.f), __float2half_rn(l.w * 2048.f)));
        }
    };

    const uint32_t a32_off = (uint32_t)((lane & 15) * G::P32 + (lane >> 4) * 16);
    const uint32_t b32_off = (uint32_t)((((lane >> 3) & 1) * 8 + (lane & 7)) * G::P32
                                        + (lane >> 4) * 16);
    const int ll = lane & 15;
    const uint32_t a16_off = (uint32_t)((wm + (lane & 15)) * G::P16 + (lane >> 4) * 16);
    const uint32_t b16_off = (uint32_t)((wn + (ll & 7)) * G::P16 + (ll >> 3) * 16);

    auto compute = [&](int s) {
        const uint32_t base = dsm + s * G::STAGE;
        const uint32_t aH = base + (uint32_t)(wm * G::P32) + a32_off;
        const uint32_t bH = base + G::OFF_B32 + (uint32_t)(wn * G::P32) + b32_off;
#pragma unroll
        for (int ks = 0; ks < 4; ks++) {
            uint32_t ah[2][4];
            uint32_t bh[4][2];
#pragma unroll
            for (int mi = 0; mi < 2; mi++)
                ldsm_x4(ah[mi], aH + mi * 16 * G::P32 + ks * 32);
#pragma unroll
            for (int p = 0; p < 2; p++) {
                uint32_t t[4];
                ldsm_x4(t, bH + p * 16 * G::P32 + ks * 32);
                bh[2*p][0] = t[0]; bh[2*p][1] = t[2];
                bh[2*p+1][0] = t[1]; bh[2*p+1][1] = t[3];
            }
#pragma unroll
            for (int mi = 0; mi < 2; mi++)
#pragma unroll
                for (int ni = 0; ni < 4; ni++)
                    mma1688(Chh[mi][ni], ah[mi], bh[ni][0], bh[ni][1]);
        }
        const uint32_t aHh = base + G::OFF_A16H + a16_off;
        const uint32_t aLh = base + G::OFF_A16L + a16_off;
        const uint32_t bHh = base + G::OFF_B16H + b16_off;
        const uint32_t bLh = base + G::OFF_B16L + b16_off;
#pragma unroll
        for (int ks = 0; ks < 2; ks++) {
            uint32_t ah16[2][4], al16[2][4], bh16[4][2], bl16[4][2];
#pragma unroll
            for (int mi = 0; mi < 2; mi++) {
                ldsm_x4(ah16[mi], aHh + mi * 16 * G::P16 + ks * 32);
                ldsm_x4(al16[mi], aLh + mi * 16 * G::P16 + ks * 32);
            }
#pragma unroll
            for (int ni = 0; ni < 4; ni++) {
                ldsm_x2(bh16[ni], bHh + ni * 8 * G::P16 + ks * 32);
                ldsm_x2(bl16[ni], bLh + ni * 8 * G::P16 + ks * 32);
            }
#pragma unroll
            for (int mi = 0; mi < 2; mi++)
#pragma unroll
                for (int ni = 0; ni < 4; ni++)
                    mma16816(Ccr[mi][ni], ah16[mi], bl16[ni]);
#pragma unroll
            for (int mi = 0; mi < 2; mi++)
#pragma unroll
                for (int ni = 0; ni < 4; ni++)
                    mma16816(Ccr[mi][ni], al16[mi], bh16[ni]);
        }
    };

    const int nch = K / G::BK;   // 16
    load_chunk(0);
    store_chunk(0);
    __syncthreads();
    for (int i = 0; i < nch; i++) {
        const int s = i & 1;
        if (i + 1 < nch) load_chunk(i + 1);
        compute(s);
        if (i + 1 < nch) {
            store_chunk(s ^ 1);
            __syncthreads();
        }
    }

    // fused epilogue: gates -> smem -> LSTM pointwise
    __syncthreads();   // all warps done reading stage smem
    constexpr int GP = 132;  // gate tile pitch (floats); 132*4 % 16 == 0
    float* gt = reinterpret_cast<float*>(smem);
    const float sc = 1.0f / 2048.0f;
#pragma unroll
    for (int mi = 0; mi < 2; mi++)
#pragma unroll
        for (int ni = 0; ni < 4; ni++)
#pragma unroll
            for (int h = 0; h < 2; h++) {
                int rl = wm + mi * 16 + (lane >> 2) + h * 8;
                int cl = wn + ni * 8 + (lane & 3) * 2;
                long row = m0 + rl;
                int  col = n0 + cl;
                float2 ad = *reinterpret_cast<const float2*>(
                    addend + row * (long)(TT * G4H) + col);
                gt[rl * GP + cl]     = Chh[mi][ni][2*h+0] + sc * Ccr[mi][ni][2*h+0] + ad.x;
                gt[rl * GP + cl + 1] = Chh[mi][ni][2*h+1] + sc * Ccr[mi][ni][2*h+1] + ad.y;
            }
    __syncthreads();

    const int u0 = n0 >> 2;  // first LSTM unit handled by this CTA (32 units)
    for (int q = tid; q < 128 * 32; q += 512) {
        int r = q >> 5;
        int u = q & 31;
        float4 g4 = *reinterpret_cast<float4*>(gt + r * GP + u * 4);  // i,f,g,o
        size_t idx = (size_t)(m0 + r) * HH + (u0 + u);
        float cold = Cs[idx];
        float c = sigmoidf(g4.y) * cold + sigmoidf(g4.x) * tanhf(g4.z);
        Cs[idx] = c;
        Hout[idx] = sigmoidf(g4.w) * tanhf(c);
    }
}

// ------------------------- small kernels -------------------------
__global__ void zero_kernel(float* __restrict__ p, size_t n) {
    size_t i = (size_t)blockIdx.x * blockDim.x + threadIdx.x;
    if (i < n) p[i] = 0.f;
}

// permute LSTM weights to gate-interleaved layout: n -> 4*(n%512) + n/512
__global__ void perm_kernel(const float* __restrict__ Wih, const float* __restrict__ Whh,
                            const float* __restrict__ bih, const float* __restrict__ bhh,
                            float* __restrict__ Wih2, float* __restrict__ Whh2,
                            float* __restrict__ bsum2) {
    int n = blockIdx.x;
    int np = 4 * (n & 511) + (n >> 9);
    for (int i = threadIdx.x; i < DD; i += blockDim.x)
        Wih2[(size_t)np * DD + i] = Wih[(size_t)n * DD + i];
    for (int i = threadIdx.x; i < HH; i += blockDim.x)
        Whh2[(size_t)np * HH + i] = Whh[(size_t)n * HH + i];
    if (threadIdx.x == 0) bsum2[np] = bih[n] + bhh[n];
}

// t=0 LSTM pointwise on interleaved XS (h0 = c0 = 0)
__global__ void lstm0_il(const float* __restrict__ XS0, float* __restrict__ Hs,
                         float* __restrict__ Cs) {
    int idx = blockIdx.x * blockDim.x + threadIdx.x;
    if (idx >= BATCH * HH) return;
    int b = idx / HH, j = idx % HH;
    float4 g4 = *reinterpret_cast<const float4*>(XS0 + (size_t)b * (TT * G4H) + 4 * j);
    float c = sigmoidf(g4.x) * tanhf(g4.z);
    Cs[idx] = c;
    Hs[idx] = sigmoidf(g4.w) * tanhf(c);
}

__global__ void flow2_kernel(const float* __restrict__ FHp,
                             const float* __restrict__ fw2,
                             const float* __restrict__ fb2,
                             float* __restrict__ FLOWp,
                             float* __restrict__ out) {
    __shared__ float w[NF * HH];
    int tid = threadIdx.x;
    for (int q = tid; q < NF * HH; q += blockDim.x) w[q] = fw2[q];
    __syncthreads();
    int warp = tid >> 5, lane = tid & 31;
    int b = blockIdx.x * 8 + warp;
    const float* r = FHp + (size_t)b * HH;
    float a0 = 0.f, a1 = 0.f, a2 = 0.f, a3 = 0.f;
    for (int k = lane; k < HH; k += 32) {
        float v = r[k];
        a0 += v * w[k];
        a1 += v * w[HH + k];
        a2 += v * w[2 * HH + k];
        a3 += v * w[3 * HH + k];
    }
#pragma unroll
    for (int off = 16; off; off >>= 1) {
        a0 += __shfl_xor_sync(0xffffffffu, a0, off);
        a1 += __shfl_xor_sync(0xffffffffu, a1, off);
        a2 += __shfl_xor_sync(0xffffffffu, a2, off);
        a3 += __shfl_xor_sync(0xffffffffu, a3, off);
    }
    if (lane == 0) {
        a0 += fb2[0]; a1 += fb2[1]; a2 += fb2[2]; a3 += fb2[3];
        float m = fmaxf(fmaxf(a0, a1), fmaxf(a2, a3));
        float e0 = expf(a0 - m), e1 = expf(a1 - m), e2 = expf(a2 - m), e3 = expf(a3 - m);
        float inv = 1.f / (e0 + e1 + e2 + e3);
        float p0 = e0 * inv, p1 = e1 * inv, p2 = e2 * inv, p3 = e3 * inv;
        FLOWp[b * 4 + 0] = p0; FLOWp[b * 4 + 1] = p1;
        FLOWp[b * 4 + 2] = p2; FLOWp[b * 4 + 3] = p3;
        out[OFF_FLOW + b * 4 + 0] = p0; out[OFF_FLOW + b * 4 + 1] = p1;
        out[OFF_FLOW + b * 4 + 2] = p2; out[OFF_FLOW + b * 4 + 3] = p3;
    }
}

__global__ void build_comb(const float* __restrict__ x,
                           const float* __restrict__ Hs,
                           const float* __restrict__ FLOWp,
                           float* __restrict__ comb) {
    size_t idx = (size_t)blockIdx.x * blockDim.x + threadIdx.x;
    if (idx >= (size_t)BATCH * KCOMB) return;
    int b = (int)(idx / KCOMB), c = (int)(idx % KCOMB);
    float v;
    if (c < DD)            v = x[(size_t)b * DD + c];
    else if (c < DD + HH)  v = Hs[(size_t)b * HH + (c - DD)];
    else                   v = FLOWp[b * 4 + (c - DD - HH)];
    comb[idx] = v;
}

__global__ void final_gate_kernel(const float* __restrict__ adjraw,
                                  const float* __restrict__ flow,
                                  const float* __restrict__ spec,
                                  float* __restrict__ out) {
    __shared__ float s_spec[EE * NF];
    __shared__ float s_usage[EE];
    int tid = threadIdx.x;
    if (tid < EE * NF) s_spec[tid] = spec[tid];
    if (tid < EE)      s_usage[tid] = 0.f;
    __syncthreads();

    int warp = tid >> 5, lane = tid & 31;
    int b = blockIdx.x * 8 + warp;

    float f0 = flow[b * 4 + 0], f1 = flow[b * 4 + 1], f2 = flow[b * 4 + 2], f3 = flow[b * 4 + 3];
    int e0 = lane, e1 = lane + 32;
    float sp0 = 0.1f * (f0 * s_spec[e0 * 4 + 0] + f1 * s_spec[e0 * 4 + 1] +
                        f2 * s_spec[e0 * 4 + 2] + f3 * s_spec[e0 * 4 + 3]);
    float sp1 = 0.1f * (f0 * s_spec[e1 * 4 + 0] + f1 * s_spec[e1 * 4 + 1] +
                        f2 * s_spec[e1 * 4 + 2] + f3 * s_spec[e1 * 4 + 3]);
    float l0 = adjraw[(size_t)b * EE + e0] + sp0;
    float l1 = adjraw[(size_t)b * EE + e1] + sp1;
    out[OFF_ADJ + (size_t)b * EE + e0] = l0;
    out[OFF_ADJ + (size_t)b * EE + e1] = l1;

    float m = fmaxf(l0, l1);
#pragma unroll
    for (int off = 16; off; off >>= 1) m = fmaxf(m, __shfl_xor_sync(0xffffffffu, m, off));
    float x0 = expf(l0 - m), x1 = expf(l1 - m);
    float s = x0 + x1;
#pragma unroll
    for (int off = 16; off; off >>= 1) s += __shfl_xor_sync(0xffffffffu, s, off);
    float inv_s = 1.f / s;
    float p0 = x0 * inv_s, p1 = x1 * inv_s;

    atomicAdd(&s_usage[e0], p0);
    atomicAdd(&s_usage[e1], p1);

    float tp[8]; int ti[8];
    float v0 = p0, v1 = p1;
#pragma unroll
    for (int it = 0; it < 8; it++) {
        float v; int bi;
        if (v1 > v0) { v = v1; bi = e1; } else { v = v0; bi = e0; }
#pragma unroll
        for (int off = 16; off; off >>= 1) {
            float ov = __shfl_xor_sync(0xffffffffu, v, off);
            int   oi = __shfl_xor_sync(0xffffffffu, bi, off);
            if (ov > v || (ov == v && oi < bi)) { v = ov; bi = oi; }
        }
        tp[it] = v; ti[it] = bi;
        if (bi == e0) v0 = -1.f;
        if (bi == e1) v1 = -1.f;
    }
    float ssum = 0.f;
#pragma unroll
    for (int it = 0; it < 8; it++) ssum += tp[it];
    float invn = 1.f / (ssum + 1e-8f);
    if (lane < 8) {
        out[OFF_TOPP + (size_t)b * 8 + lane] = tp[lane] * invn;
        out[OFF_TOPI + (size_t)b * 8 + lane] = (float)ti[lane];
    }
    __syncthreads();
    if (tid < EE) atomicAdd(&out[OFF_USAGE + tid], s_usage[tid]);
}

__global__ void loss_kernel(float* __restrict__ out) {
    __shared__ float red[EE];
    int t = threadIdx.x;  // 64 threads
    float u = out[OFF_USAGE + t] / (float)BATCH;
    out[OFF_USAGE + t] = u;
    red[t] = -(1.0f / 64.f) * log1pf(64.f * u - 1.f);
    __syncthreads();
    for (int s = 32; s; s >>= 1) {
        if (t < s) red[t] += red[t + s];
        __syncthreads();
    }
    if (t == 0) out[OFF_LOSS] = red[0] / 64.f;
}

// ------------------------- launch -------------------------
extern "C" void kernel_launch(void* const* d_in, const int* in_sizes, int n_in,
                              void* d_out, int out_size) {
    const float* x        = (const float*)d_in[0];
    const float* context  = (const float*)d_in[1];
    const float* W_ih     = (const float*)d_in[2];
    const float* W_hh     = (const float*)d_in[3];
    const float* b_ih     = (const float*)d_in[4];
    const float* b_hh     = (const float*)d_in[5];
    const float* fw1      = (const float*)d_in[6];
    const float* fb1      = (const float*)d_in[7];
    const float* fw2      = (const float*)d_in[8];
    const float* fb2      = (const float*)d_in[9];
    const float* gw1      = (const float*)d_in[10];
    const float* gb1      = (const float*)d_in[11];
    const float* gw2      = (const float*)d_in[12];
    const float* gb2      = (const float*)d_in[13];
    const float* espec    = (const float*)d_in[14];
    float* out = (float*)d_out;

    float *XS, *Ha, *Hb, *Cs, *FH, *FLOW, *COMB, *G1, *ADJ, *WIH2, *WHH2, *BSUM2;
    cudaGetSymbolAddress((void**)&XS,    d_XS);
    cudaGetSymbolAddress((void**)&Ha,    d_Hst);
    cudaGetSymbolAddress((void**)&Hb,    d_Hst2);
    cudaGetSymbolAddress((void**)&Cs,    d_Cst);
    cudaGetSymbolAddress((void**)&FH,    d_FH);
    cudaGetSymbolAddress((void**)&FLOW,  d_FLOW);
    cudaGetSymbolAddress((void**)&COMB,  d_COMB);
    cudaGetSymbolAddress((void**)&G1,    d_G1);
    cudaGetSymbolAddress((void**)&ADJ,   d_ADJ);
    cudaGetSymbolAddress((void**)&WIH2,  d_WIH2);
    cudaGetSymbolAddress((void**)&WHH2,  d_WHH2);
    cudaGetSymbolAddress((void**)&BSUM2, d_BSUM2);

    const int SMEM128 = 2 * ((128 + 128) * 144 + 2 * (128 + 128) * 80);  // 155648
    const int SMEM64  = 2 * ((128 + 64) * 144 + 2 * (128 + 64) * 80);    // 116736
    cudaFuncSetAttribute(gemm_mma<128>, cudaFuncAttributeMaxDynamicSharedMemorySize, SMEM128);
    cudaFuncSetAttribute(gemm_mma<64>,  cudaFuncAttributeMaxDynamicSharedMemorySize, SMEM64);
    cudaFuncSetAttribute(gemm_lstm,     cudaFuncAttributeMaxDynamicSharedMemorySize, SMEM128);

    // 1: permute LSTM weights + bias to gate-interleaved layout
    perm_kernel<<<G4H, 256>>>(W_ih, W_hh, b_ih, b_hh, WIH2, WHH2, BSUM2);

    // 2: flow hidden: relu(x @ fw1^T + fb1)
    gemm_mma<128><<<dim3(HH / 128, BATCH / 128), 512, SMEM128>>>(
        x, DD, fw1, DD, FH, HH, DD, fb1, nullptr, 0, 1);

    // 3: flow_state softmax head
    flow2_kernel<<<BATCH / 8, 256>>>(FH, fw2, fb2, FLOW, out);

    // 4: XS = context @ WIH2^T + BSUM2 (interleaved cols)  <-- profiled slot
    gemm_mma<128><<<dim3(G4H / 128, (BATCH * TT) / 128), 512, SMEM128>>>(
        context, DD, WIH2, DD, XS, G4H, DD, BSUM2, nullptr, 0, 0);

    // 5: t = 0 pointwise (h0 = c0 = 0), interleaved XS
    lstm0_il<<<(BATCH * HH + 255) / 256, 256>>>(XS, Ha, Cs);

    // 6..12: fused recurrent GEMM + LSTM pointwise, double-buffered H
    float* Hin = Ha;
    float* Hout = Hb;
    for (int t = 1; t < TT; t++) {
        gemm_lstm<<<dim3(G4H / 128, BATCH / 128), 512, SMEM128>>>(
            Hin, WHH2, XS + (size_t)t * G4H, Hout, Cs);
        float* tmp = Hin; Hin = Hout; Hout = tmp;
    }
    // final hidden state is in Hin after the loop

    build_comb<<<(unsigned)(((size_t)BATCH * KCOMB + 255) / 256), 256>>>(x, Hin, FLOW, COMB);

    // gate hidden: relu(combined @ gw1^T + gb1), K = 1540
    gemm_mma<128><<<dim3(DD / 128, BATCH / 128), 512, SMEM128>>>(
        COMB, KCOMB, gw1, KCOMB, G1, DD, KCOMB, gb1, nullptr, 0, 1);

    // gate logits: G1 @ gw2^T + gb2
    gemm_mma<64><<<dim3(EE / 64, BATCH / 128), 256, SMEM64>>>(
        G1, DD, gw2, DD, ADJ, EE, DD, gb2, nullptr, 0, 0);

    zero_kernel<<<1, 64>>>(out + OFF_USAGE, EE);
    final_gate_kernel<<<BATCH / 8, 256>>>(ADJ, FLOW, espec, out);
    loss_kernel<<<1, 64>>>(out);
}